// round 7
// baseline (speedup 1.0000x reference)
#include <cuda_runtime.h>
#include <cuda_bf16.h>
#include <cstdint>
#include <math.h>

#define B_   2
#define L_   1024
#define HS_  2048
#define NH_  8
#define HD_  256
#define DV_  512
#define KD_  2048
#define VD_  4096
#define E_   3
#define TOK_ 2048
#define NV_  8
#define DVS_ 64

// ---------------- scratch (static device arrays; no allocation) ----------------
__device__ __align__(16) float g_xq[TOK_*KD_];
__device__ __align__(16) float g_xk[TOK_*KD_];
__device__ __align__(16) float g_xv[TOK_*VD_];
__device__ __align__(16) float g_xg[TOK_*VD_];
__device__ __align__(16) float g_q [TOK_*KD_];
__device__ __align__(16) float g_k [TOK_*KD_];
__device__ __align__(16) float g_v [TOK_*VD_];
__device__ __align__(16) float g_ke[E_*TOK_*KD_];
__device__ __align__(16) float g_betaA[TOK_*E_*NH_];
__device__ __align__(16) float g_aA  [TOK_*E_*NH_];
__device__ __align__(16) float g_dec [E_*B_*NH_*L_];
__device__ __align__(16) float g_bm  [E_*B_*NH_*L_];
__device__ __align__(16) float g_opre[TOK_*VD_];

// split-bf16 buffers: A-side layout [hi | lo | hi], B-side layout [hi | hi | lo]
__device__ __align__(16) __nv_bfloat16 g_X3 [TOK_*3*HS_];
__device__ __align__(16) __nv_bfloat16 g_Wq3[KD_*3*HS_];
__device__ __align__(16) __nv_bfloat16 g_Wk3[KD_*3*HS_];
__device__ __align__(16) __nv_bfloat16 g_Wv3[VD_*3*HS_];
__device__ __align__(16) __nv_bfloat16 g_Wg3[VD_*3*HS_];
__device__ __align__(16) __nv_bfloat16 g_Wo3[HS_*3*VD_];
__device__ __align__(16) __nv_bfloat16 g_of3[TOK_*3*VD_];

// ======================= helpers =============================================
__device__ __forceinline__ void cp16(uint32_t dst, const void* src) {
    asm volatile("cp.async.cg.shared.global [%0], [%1], 16;" :: "r"(dst), "l"(src));
}
#define CP_COMMIT() asm volatile("cp.async.commit_group;" ::: "memory")
#define CP_WAIT(n)  asm volatile("cp.async.wait_group %0;" :: "n"(n) : "memory")

#define MMA16816(d, a0, a1, a2, a3, b0, b1) \
    asm volatile("mma.sync.aligned.m16n8k16.row.col.f32.bf16.bf16.f32 " \
                 "{%0,%1,%2,%3}, {%4,%5,%6,%7}, {%8,%9}, {%0,%1,%2,%3};" \
                 : "+f"((d)[0]), "+f"((d)[1]), "+f"((d)[2]), "+f"((d)[3]) \
                 : "r"(a0), "r"(a1), "r"(a2), "r"(a3), "r"(b0), "r"(b1))

// packed f32x2 (Blackwell)
typedef unsigned long long u64;
__device__ __forceinline__ u64 pack2(float x, float y) {
    u64 r; asm("mov.b64 %0, {%1, %2};" : "=l"(r) : "f"(x), "f"(y)); return r;
}
__device__ __forceinline__ float2 unpack2(u64 v) {
    float2 f; asm("mov.b64 {%0, %1}, %2;" : "=f"(f.x), "=f"(f.y) : "l"(v)); return f;
}
#define FMA2(d, a, b, c) \
    asm("fma.rn.f32x2 %0, %1, %2, %3;" : "=l"(d) : "l"(a), "l"(b), "l"(c))
#define MUL2(d, a, b) \
    asm("mul.rn.f32x2 %0, %1, %2;" : "=l"(d) : "l"(a), "l"(b))

// ============== HMMA split-bf16 GEMM: C[M,N] = A3[M,K3] * B3[N,K3]^T ===========
// tile 128x128, BK=32, 256 threads (8 warps, 2x4), double-buffered cp.async.
// smem row stride 40 bf16 (80B) -> conflict-free quad-pattern LDS.32.
#define BKC 32
#define SROW 40
#define STILE (128 * SROW)   // elements per operand tile

__global__ __launch_bounds__(256) void hmma_gemm(
    const __nv_bfloat16* __restrict__ A, const __nv_bfloat16* __restrict__ B,
    float* __restrict__ C, int K3, int ldc)
{
    __shared__ __nv_bfloat16 sm[2][2][STILE];   // [buf][A/B][...]
    const int tid = threadIdx.x;
    const int bm = blockIdx.y * 128;
    const int bn = blockIdx.x * 128;
    const int lane = tid & 31, wid = tid >> 5;
    const int wm = wid >> 2;          // 0..1 -> 64 rows
    const int wn = wid & 3;           // 0..3 -> 32 cols
    const int grp = lane >> 2;        // 0..7
    const int qd  = lane & 3;         // 0..3
    const uint32_t sbase = (uint32_t)__cvta_generic_to_shared(&sm[0][0][0]);

    const int NC = K3 / BKC;

    // loader: 512 x 16B per operand tile, 2+2 cp16 per thread
    const int lrow = tid >> 1;               // 0..127
    const int lch2 = (tid & 1) * 2;          // 0 or 2  (two 16B chunks each)
    const __nv_bfloat16* gA = A + (long long)(bm + lrow) * K3 + lch2 * 8;
    const __nv_bfloat16* gB = B + (long long)(bn + lrow) * K3 + lch2 * 8;
    const uint32_t sA0 = sbase + (uint32_t)(lrow * SROW + lch2 * 8) * 2;
    const uint32_t sB0 = sA0 + (uint32_t)STILE * 2;

    auto load_chunk = [&](int c, int s) {
        uint32_t off = (uint32_t)(s * 2 * STILE) * 2;
        const __nv_bfloat16* pa = gA + (long long)c * BKC;
        const __nv_bfloat16* pb = gB + (long long)c * BKC;
        cp16(sA0 + off,      pa);
        cp16(sA0 + off + 16, pa + 8);
        cp16(sB0 + off,      pb);
        cp16(sB0 + off + 16, pb + 8);
        CP_COMMIT();
    };

    float acc[4][4][4];
#pragma unroll
    for (int i = 0; i < 4; i++)
#pragma unroll
        for (int j = 0; j < 4; j++)
#pragma unroll
            for (int r = 0; r < 4; r++) acc[i][j][r] = 0.f;

    load_chunk(0, 0);
    int s = 0;
    for (int c = 0; c < NC; ++c) {
        if (c + 1 < NC) { load_chunk(c + 1, s ^ 1); CP_WAIT(1); }
        else           { CP_WAIT(0); }
        __syncthreads();

        const uint32_t* Ab = reinterpret_cast<const uint32_t*>(sm[s][0]);
        const uint32_t* Bb = reinterpret_cast<const uint32_t*>(sm[s][1]);
#pragma unroll
        for (int kk = 0; kk < 2; ++kk) {
            const int kof = kk * 16 + qd * 2;
            uint32_t af[4][4];
#pragma unroll
            for (int mt = 0; mt < 4; ++mt) {
                int r0 = wm * 64 + mt * 16 + grp;
                const uint32_t* p = Ab + ((r0 * SROW + kof) >> 1);
                af[mt][0] = p[0];
                af[mt][1] = p[(8 * SROW) >> 1];
                af[mt][2] = p[4];                      // k+8 elements = +4 u32
                af[mt][3] = p[((8 * SROW) >> 1) + 4];
            }
            uint32_t bf[4][2];
#pragma unroll
            for (int nt = 0; nt < 4; ++nt) {
                int r0 = wn * 32 + nt * 8 + grp;
                const uint32_t* p = Bb + ((r0 * SROW + kof) >> 1);
                bf[nt][0] = p[0];
                bf[nt][1] = p[4];
            }
#pragma unroll
            for (int mt = 0; mt < 4; ++mt)
#pragma unroll
                for (int nt = 0; nt < 4; ++nt)
                    MMA16816(acc[mt][nt], af[mt][0], af[mt][1], af[mt][2], af[mt][3],
                             bf[nt][0], bf[nt][1]);
        }
        __syncthreads();
        s ^= 1;
    }

    // epilogue
#pragma unroll
    for (int mt = 0; mt < 4; ++mt) {
        int row0 = bm + wm * 64 + mt * 16 + grp;
#pragma unroll
        for (int nt = 0; nt < 4; ++nt) {
            int col = bn + wn * 32 + nt * 8 + qd * 2;
            *reinterpret_cast<float2*>(&C[(long long)row0 * ldc + col]) =
                make_float2(acc[mt][nt][0], acc[mt][nt][1]);
            *reinterpret_cast<float2*>(&C[(long long)(row0 + 8) * ldc + col]) =
                make_float2(acc[mt][nt][2], acc[mt][nt][3]);
        }
    }
}

// ---------------- fp32 -> split-bf16 triple layout ------------------------------
// aSide=1 -> [h | l | h] (A operand);  aSide=0 -> [h | h | l] (B operand)
__global__ void split3_kernel(const float* __restrict__ src, __nv_bfloat16* __restrict__ dst,
                              int K, int aSide)
{
    long long i = (long long)blockIdx.x * 256 + threadIdx.x;
    int row = (int)(i / K);
    int col = (int)(i - (long long)row * K);
    float x = src[i];
    __nv_bfloat16 h = __float2bfloat16(x);
    __nv_bfloat16 l = __float2bfloat16(x - __bfloat162float(h));
    long long b = (long long)row * (3LL * K) + col;
    dst[b] = h;
    dst[b + K]     = aSide ? l : h;
    dst[b + 2LL*K] = aSide ? h : l;
}

// ---------------- generic fp32 NT GEMM (kept for the small W_ek transforms) -----
__global__ __launch_bounds__(256) void sgemm_nt(
    const float* __restrict__ A, const float* __restrict__ Bm, float* __restrict__ C,
    int M, int N, int K, int lda, int ldb, int ldc,
    long long sA, long long sB, long long sC)
{
    A  += (long long)blockIdx.z * sA;
    Bm += (long long)blockIdx.z * sB;
    C  += (long long)blockIdx.z * sC;
    const int bm = blockIdx.y * 128;
    const int bn = blockIdx.x * 128;
    __shared__ float As[16][128];
    __shared__ float Bs[16][128];
    const int tid = threadIdx.x;
    const int tx = tid & 15;
    const int ty = tid >> 4;
    const int arow = tid >> 2;
    const int akq  = tid & 3;

    float acc[8][8];
#pragma unroll
    for (int i = 0; i < 8; i++)
#pragma unroll
        for (int j = 0; j < 8; j++) acc[i][j] = 0.f;

    for (int k0 = 0; k0 < K; k0 += 16) {
#pragma unroll
        for (int p = 0; p < 2; ++p) {
            int r = arow + p * 64;
            float4 va = *reinterpret_cast<const float4*>(&A [(long long)(bm + r) * lda + k0 + akq * 4]);
            As[akq*4+0][r] = va.x; As[akq*4+1][r] = va.y;
            As[akq*4+2][r] = va.z; As[akq*4+3][r] = va.w;
            float4 vb = *reinterpret_cast<const float4*>(&Bm[(long long)(bn + r) * ldb + k0 + akq * 4]);
            Bs[akq*4+0][r] = vb.x; Bs[akq*4+1][r] = vb.y;
            Bs[akq*4+2][r] = vb.z; Bs[akq*4+3][r] = vb.w;
        }
        __syncthreads();
#pragma unroll
        for (int kk = 0; kk < 16; ++kk) {
            float a[8], b[8];
            *reinterpret_cast<float4*>(&a[0]) = *reinterpret_cast<const float4*>(&As[kk][ty*8]);
            *reinterpret_cast<float4*>(&a[4]) = *reinterpret_cast<const float4*>(&As[kk][ty*8+4]);
            *reinterpret_cast<float4*>(&b[0]) = *reinterpret_cast<const float4*>(&Bs[kk][tx*8]);
            *reinterpret_cast<float4*>(&b[4]) = *reinterpret_cast<const float4*>(&Bs[kk][tx*8+4]);
#pragma unroll
            for (int i = 0; i < 8; i++)
#pragma unroll
                for (int j = 0; j < 8; j++) acc[i][j] += a[i] * b[j];
        }
        __syncthreads();
    }
#pragma unroll
    for (int i = 0; i < 8; i++) {
        long long roff = (long long)(bm + ty*8 + i) * ldc + bn + tx*8;
        *reinterpret_cast<float4*>(&C[roff])     = make_float4(acc[i][0], acc[i][1], acc[i][2], acc[i][3]);
        *reinterpret_cast<float4*>(&C[roff + 4]) = make_float4(acc[i][4], acc[i][5], acc[i][6], acc[i][7]);
    }
}

// ------------- small projection: beta_raw / a_raw = X @ {Wb,Wa}^T ---------------
__global__ __launch_bounds__(256) void proj_ba_kernel(
    const float* __restrict__ X, const float* __restrict__ Wb, const float* __restrict__ Wa,
    float* __restrict__ outB, float* __restrict__ outA)
{
    __shared__ float xs[HS_];
    int tok = blockIdx.x;
    const float* xr = X + (long long)tok * HS_;
    for (int i = threadIdx.x * 4; i < HS_; i += 256 * 4)
        *reinterpret_cast<float4*>(&xs[i]) = *reinterpret_cast<const float4*>(&xr[i]);
    __syncthreads();
    int warp = threadIdx.x >> 5, lane = threadIdx.x & 31;
    for (int j = warp; j < E_ * NH_; j += 8) {
        const float* wb = Wb + (long long)j * HS_;
        const float* wa = Wa + (long long)j * HS_;
        float sb = 0.f, sa = 0.f;
        for (int i = lane * 4; i < HS_; i += 32 * 4) {
            float4 xv = *reinterpret_cast<const float4*>(&xs[i]);
            float4 bv = *reinterpret_cast<const float4*>(&wb[i]);
            float4 av = *reinterpret_cast<const float4*>(&wa[i]);
            sb += xv.x*bv.x + xv.y*bv.y + xv.z*bv.z + xv.w*bv.w;
            sa += xv.x*av.x + xv.y*av.y + xv.z*av.z + xv.w*av.w;
        }
#pragma unroll
        for (int off = 16; off; off >>= 1) {
            sb += __shfl_xor_sync(0xffffffffu, sb, off);
            sa += __shfl_xor_sync(0xffffffffu, sa, off);
        }
        if (lane == 0) {
            outB[tok * (E_*NH_) + j] = sb;
            outA[tok * (E_*NH_) + j] = sa;
        }
    }
}

// ---------------- causal depthwise conv (K=4) + SiLU ---------------------------
__global__ void conv_silu_kernel(const float* __restrict__ xin, const float* __restrict__ w,
                                 float* __restrict__ out, int C)
{
    int c  = blockIdx.x * 256 + threadIdx.x;
    int b  = blockIdx.z;
    int l0 = blockIdx.y * 64;
    float w0 = w[c*4+0], w1 = w[c*4+1], w2 = w[c*4+2], w3 = w[c*4+3];
    const float* xb = xin + (long long)b * L_ * C + c;
    float*       ob = out + (long long)b * L_ * C + c;
    float xm3 = (l0 >= 3) ? xb[(l0-3)*C] : 0.f;
    float xm2 = (l0 >= 2) ? xb[(l0-2)*C] : 0.f;
    float xm1 = (l0 >= 1) ? xb[(l0-1)*C] : 0.f;
    for (int l = l0; l < l0 + 64; ++l) {
        float x0 = xb[l*C];
        float y  = w0*xm3 + w1*xm2 + w2*xm1 + w3*x0;
        ob[l*C]  = y / (1.f + expf(-y));
        xm3 = xm2; xm2 = xm1; xm1 = x0;
    }
}

// ---------------- l2 normalize rows of 256 (optionally * scale) ----------------
__global__ void l2norm_kernel(float* __restrict__ data, float scale)
{
    int warp = threadIdx.x >> 5;
    int lane = threadIdx.x & 31;
    long long row = (long long)blockIdx.x * 8 + warp;
    float* p = data + row * HD_ + lane * 8;
    float4 a = *reinterpret_cast<float4*>(p);
    float4 b = *reinterpret_cast<float4*>(p + 4);
    float s = a.x*a.x + a.y*a.y + a.z*a.z + a.w*a.w
            + b.x*b.x + b.y*b.y + b.z*b.z + b.w*b.w;
#pragma unroll
    for (int off = 16; off; off >>= 1) s += __shfl_xor_sync(0xffffffffu, s, off);
    float r = rsqrtf(s + 1e-6f) * scale;
    a.x *= r; a.y *= r; a.z *= r; a.w *= r;
    b.x *= r; b.y *= r; b.z *= r; b.w *= r;
    *reinterpret_cast<float4*>(p)     = a;
    *reinterpret_cast<float4*>(p + 4) = b;
}

// ---------------- gating: decay and beta*mask per (e,b,h,t) --------------------
__global__ void gating_kernel(const float* __restrict__ betaA, const float* __restrict__ aA,
                              const int* __restrict__ mod, const float* __restrict__ A_log,
                              const float* __restrict__ dtb,
                              float* __restrict__ dec, float* __restrict__ bm)
{
    int idx = blockIdx.x * 256 + threadIdx.x;
    if (idx >= E_*B_*NH_*L_) return;
    int t = idx % L_;
    int h = (idx / L_) % NH_;
    int b = (idx / (L_*NH_)) % B_;
    int e = idx / (L_*NH_*B_);
    int tok = b * L_ + t;
    int j = e * NH_ + h;
    float braw = betaA[tok*(E_*NH_) + j];
    float beta = 1.f / (1.f + expf(-braw));
    float av = aA[tok*(E_*NH_) + j] + dtb[j];
    float sp = (av > 20.f) ? av : log1pf(expf(av));
    float g  = -expf(A_log[j]) * sp;
    int mid  = mod[tok];
    float m  = (e == 0) ? 1.f : ((e == 1) ? (mid == 0 ? 1.f : 0.f)
                                          : (mid == 1 ? 1.f : 0.f));
    dec[idx] = expf(g) * m + (1.f - m);
    bm[idx]  = beta * m;
}

// ---------------- zero fill -----------------------------------------------------
__global__ void zero_kernel(float4* __restrict__ p, int n4)
{
    int i = blockIdx.x * 256 + threadIdx.x;
    if (i < n4) p[i] = make_float4(0.f, 0.f, 0.f, 0.f);
}

// ------- recurrent scan: packed-f32x2 register state, v-partitioned -------------
// grid: E*B*NH*NV_ CTAs of 128 threads, 3 CTAs/SM (single wave: 384 <= 444).
// thread: v_local = tid>>1 (0..63), k-half = tid&1. State = 64 f32x2 pairs.
__global__ __launch_bounds__(128, 3) void scan_kernel(
    const float* __restrict__ qbuf, const float* __restrict__ kebuf,
    const float* __restrict__ vbuf, const float* __restrict__ decbuf,
    const float* __restrict__ bmbuf, const float* __restrict__ oww,
    float* __restrict__ opre)
{
    const int cta = blockIdx.x;
    const int vp = cta % NV_;
    const int h  = (cta / NV_) % NH_;
    const int b  = (cta / (NV_ * NH_)) % B_;
    const int e  = cta / (NV_ * NH_ * B_);
    const int tid = threadIdx.x;
    const int vl = tid >> 1;
    const int kh = tid & 1;
    const int vbase = vp * DVS_;

    float w0 = expf(oww[0*NH_ + h]);
    float w1 = expf(oww[1*NH_ + h]);
    float w2 = expf(oww[2*NH_ + h]);
    float wout = ((e == 0) ? w0 : ((e == 1) ? w1 : w2)) / (w0 + w1 + w2);

    __shared__ __align__(16) float ksm[2][264];
    __shared__ __align__(16) float qsm[2][264];

    u64 S2[64];
    const u64 z2 = pack2(0.f, 0.f);
#pragma unroll
    for (int j = 0; j < 64; j++) S2[j] = z2;

    const float* decp = decbuf + ((e*B_ + b)*NH_ + h) * L_;
    const float* bmp  = bmbuf  + ((e*B_ + b)*NH_ + h) * L_;
    const float* kp   = kebuf + (long long)e * TOK_ * KD_ + (long long)b * L_ * KD_ + h * HD_;
    const float* qp   = qbuf  + (long long)b * L_ * KD_ + h * HD_;
    const float* vp_  = vbuf  + (long long)b * L_ * VD_ + h * DV_ + vbase + vl;
    float*       op   = opre  + (long long)b * L_ * VD_ + h * DV_ + vbase + vl;

    const int koff = kh * 132;          // 132 floats = 528 B (16B aligned)
    const int idx4 = tid & 63;
    const int halfoff = ((idx4 >> 5) * 132) + ((idx4 * 4) & 127);
    const bool loadk = (tid < 64);
    const float* mysrc = loadk ? kp : qp;

    // preload t = 0
    {
        float4 v4 = *reinterpret_cast<const float4*>(mysrc + idx4 * 4);
        float* dst = loadk ? &ksm[0][0] : &qsm[0][0];
        *reinterpret_cast<float4*>(dst + halfoff) = v4;
    }
    float dec_c = decp[0], bm_c = bmp[0], v_c = vp_[0];
    __syncthreads();

    for (int t = 0; t < L_; ++t) {
        const int cur = t & 1;
        float dec_n = 0.f, bm_n = 0.f, v_n = 0.f;
        if (t + 1 < L_) {
            float4 v4 = *reinterpret_cast<const float4*>(mysrc + (long long)(t+1) * KD_ + idx4 * 4);
            float* dst = loadk ? &ksm[cur ^ 1][0] : &qsm[cur ^ 1][0];
            *reinterpret_cast<float4*>(dst + halfoff) = v4;
            dec_n = decp[t+1]; bm_n = bmp[t+1]; v_n = vp_[(long long)(t+1) * VD_];
        }
        const float* kb = &ksm[cur][koff];
        const float* qb = &qsm[cur][koff];

        // pass 1: decay + predicted value  pred = sum_k k_k * (dec * S[k])
        const u64 dd = pack2(dec_c, dec_c);
        u64 a0 = z2, a1 = z2;
#pragma unroll
        for (int j = 0; j < 128; j += 4) {
            ulonglong2 kk = *reinterpret_cast<const ulonglong2*>(kb + j);
            const int i = j >> 1;
            MUL2(S2[i],   S2[i],   dd);
            FMA2(a0, kk.x, S2[i],   a0);
            MUL2(S2[i+1], S2[i+1], dd);
            FMA2(a1, kk.y, S2[i+1], a1);
        }
        float2 f0 = unpack2(a0), f1 = unpack2(a1);
        float pred = (f0.x + f0.y) + (f1.x + f1.y);
        pred += __shfl_xor_sync(0xffffffffu, pred, 1);
        float delta = (v_c - pred) * bm_c;
        const u64 del2 = pack2(delta, delta);

        // pass 2: rank-1 update + output  o = sum_k q_k * S[k]
        u64 b0 = z2, b1 = z2;
#pragma unroll
        for (int j = 0; j < 128; j += 4) {
            ulonglong2 kk = *reinterpret_cast<const ulonglong2*>(kb + j);
            ulonglong2 qq = *reinterpret_cast<const ulonglong2*>(qb + j);
            const int i = j >> 1;
            FMA2(S2[i],   kk.x, del2, S2[i]);
            FMA2(b0, qq.x, S2[i],   b0);
            FMA2(S2[i+1], kk.y, del2, S2[i+1]);
            FMA2(b1, qq.y, S2[i+1], b1);
        }
        float2 g0 = unpack2(b0), g1 = unpack2(b1);
        float o = (g0.x + g0.y) + (g1.x + g1.y);
        o += __shfl_xor_sync(0xffffffffu, o, 1);
        if (kh == 0) atomicAdd(&op[(long long)t * VD_], o * wout);

        __syncthreads();
        dec_c = dec_n; bm_c = bm_n; v_c = v_n;
    }
}

// -------- RMSNorm * weight * SiLU(gate), emitting split-bf16 A-operand ----------
__global__ __launch_bounds__(128) void norm_gate_kernel(
    const float* __restrict__ opre, const float* __restrict__ xg,
    const float* __restrict__ wnorm, __nv_bfloat16* __restrict__ out3)
{
    int row = blockIdx.x;                       // tok*NH + h
    long long base = (long long)row * DV_;
    const float* o = opre + base;
    const float* g = xg + base;
    int i = threadIdx.x * 4;
    float4 ov = *reinterpret_cast<const float4*>(&o[i]);
    float ss = ov.x*ov.x + ov.y*ov.y + ov.z*ov.z + ov.w*ov.w;
#pragma unroll
    for (int off = 16; off; off >>= 1) ss += __shfl_xor_sync(0xffffffffu, ss, off);
    __shared__ float red[4];
    int warp = threadIdx.x >> 5, lane = threadIdx.x & 31;
    if (lane == 0) red[warp] = ss;
    __syncthreads();
    float tot = red[0] + red[1] + red[2] + red[3];
    float inv = rsqrtf(tot * (1.f / (float)DV_) + 1e-5f);
    float4 wv = *reinterpret_cast<const float4*>(&wnorm[i]);
    float4 gv = *reinterpret_cast<const float4*>(&g[i]);
    float r[4];
    r[0] = ov.x * inv * wv.x * (gv.x / (1.f + expf(-gv.x)));
    r[1] = ov.y * inv * wv.y * (gv.y / (1.f + expf(-gv.y)));
    r[2] = ov.z * inv * wv.z * (gv.z / (1.f + expf(-gv.z)));
    r[3] = ov.w * inv * wv.w * (gv.w / (1.f + expf(-gv.w)));
    int tok = row >> 3;
    int col = (row & 7) * DV_ + i;
    long long b3 = (long long)tok * (3LL * VD_) + col;
#pragma unroll
    for (int j = 0; j < 4; ++j) {
        __nv_bfloat16 hh = __float2bfloat16(r[j]);
        __nv_bfloat16 ll = __float2bfloat16(r[j] - __bfloat162float(hh));
        out3[b3 + j]            = hh;
        out3[b3 + VD_ + j]      = ll;
        out3[b3 + 2LL*VD_ + j]  = hh;
    }
}

// ================================ launch ======================================
extern "C" void kernel_launch(void* const* d_in, const int* in_sizes, int n_in,
                              void* d_out, int out_size)
{
    const float* X    = (const float*)d_in[0];
    const int*   mod  = (const int*)  d_in[1];
    const float* Wq   = (const float*)d_in[2];
    const float* Wk   = (const float*)d_in[3];
    const float* Wv   = (const float*)d_in[4];
    const float* cq   = (const float*)d_in[5];
    const float* ck   = (const float*)d_in[6];
    const float* cv   = (const float*)d_in[7];
    const float* Wek  = (const float*)d_in[8];
    const float* Wb   = (const float*)d_in[9];
    const float* Wa   = (const float*)d_in[10];
    const float* Alog = (const float*)d_in[11];
    const float* dtb  = (const float*)d_in[12];
    const float* ow   = (const float*)d_in[13];
    const float* Wg   = (const float*)d_in[14];
    const float* onw  = (const float*)d_in[15];
    const float* Wo   = (const float*)d_in[16];
    float* out = (float*)d_out;

    float *xq, *xk, *xv, *xg, *q, *k, *v, *ke, *ba, *aa, *dec, *bm, *opre;
    __nv_bfloat16 *X3, *Wq3, *Wk3, *Wv3, *Wg3, *Wo3, *of3;
    cudaGetSymbolAddress((void**)&xq,   g_xq);
    cudaGetSymbolAddress((void**)&xk,   g_xk);
    cudaGetSymbolAddress((void**)&xv,   g_xv);
    cudaGetSymbolAddress((void**)&xg,   g_xg);
    cudaGetSymbolAddress((void**)&q,    g_q);
    cudaGetSymbolAddress((void**)&k,    g_k);
    cudaGetSymbolAddress((void**)&v,    g_v);
    cudaGetSymbolAddress((void**)&ke,   g_ke);
    cudaGetSymbolAddress((void**)&ba,   g_betaA);
    cudaGetSymbolAddress((void**)&aa,   g_aA);
    cudaGetSymbolAddress((void**)&dec,  g_dec);
    cudaGetSymbolAddress((void**)&bm,   g_bm);
    cudaGetSymbolAddress((void**)&opre, g_opre);
    cudaGetSymbolAddress((void**)&X3,   g_X3);
    cudaGetSymbolAddress((void**)&Wq3,  g_Wq3);
    cudaGetSymbolAddress((void**)&Wk3,  g_Wk3);
    cudaGetSymbolAddress((void**)&Wv3,  g_Wv3);
    cudaGetSymbolAddress((void**)&Wg3,  g_Wg3);
    cudaGetSymbolAddress((void**)&Wo3,  g_Wo3);
    cudaGetSymbolAddress((void**)&of3,  g_of3);

    // split fp32 -> bf16 triples
    split3_kernel<<<TOK_*HS_/256, 256>>>(X,  X3,  HS_, 1);
    split3_kernel<<<KD_*HS_/256, 256>>>(Wq, Wq3, HS_, 0);
    split3_kernel<<<KD_*HS_/256, 256>>>(Wk, Wk3, HS_, 0);
    split3_kernel<<<VD_*HS_/256, 256>>>(Wv, Wv3, HS_, 0);
    split3_kernel<<<VD_*HS_/256, 256>>>(Wg, Wg3, HS_, 0);
    split3_kernel<<<HS_*VD_/256, 256>>>(Wo, Wo3, VD_, 0);

    // big projections on HMMA tensor cores (K3 = 3*HS = 6144)
    hmma_gemm<<<dim3(KD_/128, TOK_/128), 256>>>(X3, Wq3, xq, 3*HS_, KD_);
    hmma_gemm<<<dim3(KD_/128, TOK_/128), 256>>>(X3, Wk3, xk, 3*HS_, KD_);
    hmma_gemm<<<dim3(VD_/128, TOK_/128), 256>>>(X3, Wv3, xv, 3*HS_, VD_);
    hmma_gemm<<<dim3(VD_/128, TOK_/128), 256>>>(X3, Wg3, xg, 3*HS_, VD_);
    proj_ba_kernel<<<TOK_, 256>>>(X, Wb, Wa, ba, aa);

    // causal conv + SiLU
    conv_silu_kernel<<<dim3(KD_/256, L_/64, B_), 256>>>(xq, cq, q, KD_);
    conv_silu_kernel<<<dim3(KD_/256, L_/64, B_), 256>>>(xk, ck, k, KD_);
    conv_silu_kernel<<<dim3(VD_/256, L_/64, B_), 256>>>(xv, cv, v, VD_);

    // l2 norm per head row; q additionally scaled by HD^-0.5
    l2norm_kernel<<<TOK_*NH_/8, 256>>>(q, 0.0625f);
    l2norm_kernel<<<TOK_*NH_/8, 256>>>(k, 1.0f);

    // per-expert per-head key transform (small, stays fp32)
    for (int e = 0; e < E_; ++e) {
        sgemm_nt<<<dim3(2,16,8), 256>>>(
            k, Wek + (long long)e * NH_ * HD_ * HD_, ke + (long long)e * TOK_ * KD_,
            TOK_, HD_, HD_, KD_, HD_, KD_,
            (long long)HD_, (long long)HD_ * HD_, (long long)HD_);
    }

    // gating scalars
    gating_kernel<<<(E_*B_*NH_*L_ + 255)/256, 256>>>(ba, aa, mod, Alog, dtb, dec, bm);

    // zero the expert-aggregated output accumulator
    zero_kernel<<<(TOK_*VD_/4 + 255)/256, 256>>>((float4*)opre, TOK_*VD_/4);

    // the sequential scan (packed f32x2 state)
    scan_kernel<<<E_*B_*NH_*NV_, 128>>>(q, ke, v, dec, bm, ow, opre);

    // RMSNorm + swish gate -> split-bf16 A operand
    norm_gate_kernel<<<TOK_*NH_, 128>>>(opre, xg, onw, of3);

    // output projection on HMMA tensor cores (K3 = 3*VD = 12288)
    hmma_gemm<<<dim3(HS_/128, TOK_/128), 256>>>(of3, Wo3, out, 3*VD_, HS_);
}

// round 8
// speedup vs baseline: 2.2017x; 2.2017x over previous
#include <cuda_runtime.h>
#include <cuda_bf16.h>
#include <cstdint>
#include <math.h>

#define B_   2
#define L_   1024
#define HS_  2048
#define NH_  8
#define HD_  256
#define DV_  512
#define KD_  2048
#define VD_  4096
#define E_   3
#define TOK_ 2048
#define NV_  8
#define DVS_ 64

// ---------------- scratch (static device arrays; no allocation) ----------------
__device__ __align__(16) float g_xqk[TOK_*(2*KD_)];   // [tok][q|k]  stride 4096
__device__ __align__(16) float g_xvg[TOK_*(2*VD_)];   // [tok][v|g]  stride 8192
__device__ __align__(16) float g_q [TOK_*KD_];
__device__ __align__(16) float g_k [TOK_*KD_];
__device__ __align__(16) float g_v [TOK_*VD_];
__device__ __align__(16) float g_ke[E_*TOK_*KD_];
__device__ __align__(16) float g_betaA[TOK_*E_*NH_];
__device__ __align__(16) float g_aA  [TOK_*E_*NH_];
__device__ __align__(16) float g_dec [E_*B_*NH_*L_];
__device__ __align__(16) float g_bm  [E_*B_*NH_*L_];
__device__ __align__(16) float g_opre[TOK_*VD_];

// split-bf16 buffers: A-side layout [hi | lo | hi], B-side layout [hi | hi | lo]
__device__ __align__(16) __nv_bfloat16 g_X3  [TOK_*3*HS_];
__device__ __align__(16) __nv_bfloat16 g_Wqk3[(2*KD_)*3*HS_];
__device__ __align__(16) __nv_bfloat16 g_Wvg3[(2*VD_)*3*HS_];
__device__ __align__(16) __nv_bfloat16 g_Wo3 [HS_*3*VD_];
__device__ __align__(16) __nv_bfloat16 g_of3 [TOK_*3*VD_];

// ======================= helpers =============================================
__device__ __forceinline__ void cp16(uint32_t dst, const void* src) {
    asm volatile("cp.async.cg.shared.global [%0], [%1], 16;" :: "r"(dst), "l"(src));
}
#define CP_COMMIT() asm volatile("cp.async.commit_group;" ::: "memory")
#define CP_WAIT(n)  asm volatile("cp.async.wait_group %0;" :: "n"(n) : "memory")

#define MMA16816(d, a0, a1, a2, a3, b0, b1) \
    asm volatile("mma.sync.aligned.m16n8k16.row.col.f32.bf16.bf16.f32 " \
                 "{%0,%1,%2,%3}, {%4,%5,%6,%7}, {%8,%9}, {%0,%1,%2,%3};" \
                 : "+f"((d)[0]), "+f"((d)[1]), "+f"((d)[2]), "+f"((d)[3]) \
                 : "r"(a0), "r"(a1), "r"(a2), "r"(a3), "r"(b0), "r"(b1))

// ============== HMMA split-bf16 GEMM: C[M,N] = A3[M,K3] * B3[N,K3]^T ===========
// tile 128x128, BK=32, 256 threads (8 warps, 2x4), double-buffered cp.async.
// smem row stride 40 bf16 (80B) -> conflict-free quad-pattern LDS.32.
#define BKC 32
#define SROW 40
#define STILE (128 * SROW)   // elements per operand tile

__global__ __launch_bounds__(256) void hmma_gemm(
    const __nv_bfloat16* __restrict__ A, const __nv_bfloat16* __restrict__ B,
    float* __restrict__ C, int K3, int ldc)
{
    __shared__ __nv_bfloat16 sm[2][2][STILE];   // [buf][A/B][...]
    const int tid = threadIdx.x;
    const int bm = blockIdx.y * 128;
    const int bn = blockIdx.x * 128;
    const int lane = tid & 31, wid = tid >> 5;
    const int wm = wid >> 2;          // 0..1 -> 64 rows
    const int wn = wid & 3;           // 0..3 -> 32 cols
    const int grp = lane >> 2;        // 0..7
    const int qd  = lane & 3;         // 0..3
    const uint32_t sbase = (uint32_t)__cvta_generic_to_shared(&sm[0][0][0]);

    const int NC = K3 / BKC;

    // loader: 512 x 16B per operand tile, 2+2 cp16 per thread
    const int lrow = tid >> 1;               // 0..127
    const int lch2 = (tid & 1) * 2;          // 0 or 2  (two 16B chunks each)
    const __nv_bfloat16* gA = A + (long long)(bm + lrow) * K3 + lch2 * 8;
    const __nv_bfloat16* gB = B + (long long)(bn + lrow) * K3 + lch2 * 8;
    const uint32_t sA0 = sbase + (uint32_t)(lrow * SROW + lch2 * 8) * 2;
    const uint32_t sB0 = sA0 + (uint32_t)STILE * 2;

    auto load_chunk = [&](int c, int s) {
        uint32_t off = (uint32_t)(s * 2 * STILE) * 2;
        const __nv_bfloat16* pa = gA + (long long)c * BKC;
        const __nv_bfloat16* pb = gB + (long long)c * BKC;
        cp16(sA0 + off,      pa);
        cp16(sA0 + off + 16, pa + 8);
        cp16(sB0 + off,      pb);
        cp16(sB0 + off + 16, pb + 8);
        CP_COMMIT();
    };

    float acc[4][4][4];
#pragma unroll
    for (int i = 0; i < 4; i++)
#pragma unroll
        for (int j = 0; j < 4; j++)
#pragma unroll
            for (int r = 0; r < 4; r++) acc[i][j][r] = 0.f;

    load_chunk(0, 0);
    int s = 0;
    for (int c = 0; c < NC; ++c) {
        if (c + 1 < NC) { load_chunk(c + 1, s ^ 1); CP_WAIT(1); }
        else           { CP_WAIT(0); }
        __syncthreads();

        const uint32_t* Ab = reinterpret_cast<const uint32_t*>(sm[s][0]);
        const uint32_t* Bb = reinterpret_cast<const uint32_t*>(sm[s][1]);
#pragma unroll
        for (int kk = 0; kk < 2; ++kk) {
            const int kof = kk * 16 + qd * 2;
            uint32_t af[4][4];
#pragma unroll
            for (int mt = 0; mt < 4; ++mt) {
                int r0 = wm * 64 + mt * 16 + grp;
                const uint32_t* p = Ab + ((r0 * SROW + kof) >> 1);
                af[mt][0] = p[0];
                af[mt][1] = p[(8 * SROW) >> 1];
                af[mt][2] = p[4];                      // k+8 elements = +4 u32
                af[mt][3] = p[((8 * SROW) >> 1) + 4];
            }
            uint32_t bf[4][2];
#pragma unroll
            for (int nt = 0; nt < 4; ++nt) {
                int r0 = wn * 32 + nt * 8 + grp;
                const uint32_t* p = Bb + ((r0 * SROW + kof) >> 1);
                bf[nt][0] = p[0];
                bf[nt][1] = p[4];
            }
#pragma unroll
            for (int mt = 0; mt < 4; ++mt)
#pragma unroll
                for (int nt = 0; nt < 4; ++nt)
                    MMA16816(acc[mt][nt], af[mt][0], af[mt][1], af[mt][2], af[mt][3],
                             bf[nt][0], bf[nt][1]);
        }
        __syncthreads();
        s ^= 1;
    }

    // epilogue
#pragma unroll
    for (int mt = 0; mt < 4; ++mt) {
        int row0 = bm + wm * 64 + mt * 16 + grp;
#pragma unroll
        for (int nt = 0; nt < 4; ++nt) {
            int col = bn + wn * 32 + nt * 8 + qd * 2;
            *reinterpret_cast<float2*>(&C[(long long)row0 * ldc + col]) =
                make_float2(acc[mt][nt][0], acc[mt][nt][1]);
            *reinterpret_cast<float2*>(&C[(long long)(row0 + 8) * ldc + col]) =
                make_float2(acc[mt][nt][2], acc[mt][nt][3]);
        }
    }
}

// ---------------- fp32 -> split-bf16 triple layout ------------------------------
// aSide=1 -> [h | l | h] (A operand);  aSide=0 -> [h | h | l] (B operand)
__global__ void split3_kernel(const float* __restrict__ src, __nv_bfloat16* __restrict__ dst,
                              int K, int aSide)
{
    long long i = (long long)blockIdx.x * 256 + threadIdx.x;
    int row = (int)(i / K);
    int col = (int)(i - (long long)row * K);
    float x = src[i];
    __nv_bfloat16 h = __float2bfloat16(x);
    __nv_bfloat16 l = __float2bfloat16(x - __bfloat162float(h));
    long long b = (long long)row * (3LL * K) + col;
    dst[b] = h;
    dst[b + K]     = aSide ? l : h;
    dst[b + 2LL*K] = aSide ? h : l;
}

// ---------------- generic fp32 NT GEMM (kept for the small W_ek transforms) -----
__global__ __launch_bounds__(256) void sgemm_nt(
    const float* __restrict__ A, const float* __restrict__ Bm, float* __restrict__ C,
    int M, int N, int K, int lda, int ldb, int ldc,
    long long sA, long long sB, long long sC)
{
    A  += (long long)blockIdx.z * sA;
    Bm += (long long)blockIdx.z * sB;
    C  += (long long)blockIdx.z * sC;
    const int bm = blockIdx.y * 128;
    const int bn = blockIdx.x * 128;
    __shared__ float As[16][128];
    __shared__ float Bs[16][128];
    const int tid = threadIdx.x;
    const int tx = tid & 15;
    const int ty = tid >> 4;
    const int arow = tid >> 2;
    const int akq  = tid & 3;

    float acc[8][8];
#pragma unroll
    for (int i = 0; i < 8; i++)
#pragma unroll
        for (int j = 0; j < 8; j++) acc[i][j] = 0.f;

    for (int k0 = 0; k0 < K; k0 += 16) {
#pragma unroll
        for (int p = 0; p < 2; ++p) {
            int r = arow + p * 64;
            float4 va = *reinterpret_cast<const float4*>(&A [(long long)(bm + r) * lda + k0 + akq * 4]);
            As[akq*4+0][r] = va.x; As[akq*4+1][r] = va.y;
            As[akq*4+2][r] = va.z; As[akq*4+3][r] = va.w;
            float4 vb = *reinterpret_cast<const float4*>(&Bm[(long long)(bn + r) * ldb + k0 + akq * 4]);
            Bs[akq*4+0][r] = vb.x; Bs[akq*4+1][r] = vb.y;
            Bs[akq*4+2][r] = vb.z; Bs[akq*4+3][r] = vb.w;
        }
        __syncthreads();
#pragma unroll
        for (int kk = 0; kk < 16; ++kk) {
            float a[8], b[8];
            *reinterpret_cast<float4*>(&a[0]) = *reinterpret_cast<const float4*>(&As[kk][ty*8]);
            *reinterpret_cast<float4*>(&a[4]) = *reinterpret_cast<const float4*>(&As[kk][ty*8+4]);
            *reinterpret_cast<float4*>(&b[0]) = *reinterpret_cast<const float4*>(&Bs[kk][tx*8]);
            *reinterpret_cast<float4*>(&b[4]) = *reinterpret_cast<const float4*>(&Bs[kk][tx*8+4]);
#pragma unroll
            for (int i = 0; i < 8; i++)
#pragma unroll
                for (int j = 0; j < 8; j++) acc[i][j] += a[i] * b[j];
        }
        __syncthreads();
    }
#pragma unroll
    for (int i = 0; i < 8; i++) {
        long long roff = (long long)(bm + ty*8 + i) * ldc + bn + tx*8;
        *reinterpret_cast<float4*>(&C[roff])     = make_float4(acc[i][0], acc[i][1], acc[i][2], acc[i][3]);
        *reinterpret_cast<float4*>(&C[roff + 4]) = make_float4(acc[i][4], acc[i][5], acc[i][6], acc[i][7]);
    }
}

// ------------- small projection: beta_raw / a_raw = X @ {Wb,Wa}^T ---------------
__global__ __launch_bounds__(256) void proj_ba_kernel(
    const float* __restrict__ X, const float* __restrict__ Wb, const float* __restrict__ Wa,
    float* __restrict__ outB, float* __restrict__ outA)
{
    __shared__ float xs[HS_];
    int tok = blockIdx.x;
    const float* xr = X + (long long)tok * HS_;
    for (int i = threadIdx.x * 4; i < HS_; i += 256 * 4)
        *reinterpret_cast<float4*>(&xs[i]) = *reinterpret_cast<const float4*>(&xr[i]);
    __syncthreads();
    int warp = threadIdx.x >> 5, lane = threadIdx.x & 31;
    for (int j = warp; j < E_ * NH_; j += 8) {
        const float* wb = Wb + (long long)j * HS_;
        const float* wa = Wa + (long long)j * HS_;
        float sb = 0.f, sa = 0.f;
        for (int i = lane * 4; i < HS_; i += 32 * 4) {
            float4 xv = *reinterpret_cast<const float4*>(&xs[i]);
            float4 bv = *reinterpret_cast<const float4*>(&wb[i]);
            float4 av = *reinterpret_cast<const float4*>(&wa[i]);
            sb += xv.x*bv.x + xv.y*bv.y + xv.z*bv.z + xv.w*bv.w;
            sa += xv.x*av.x + xv.y*av.y + xv.z*av.z + xv.w*av.w;
        }
#pragma unroll
        for (int off = 16; off; off >>= 1) {
            sb += __shfl_xor_sync(0xffffffffu, sb, off);
            sa += __shfl_xor_sync(0xffffffffu, sa, off);
        }
        if (lane == 0) {
            outB[tok * (E_*NH_) + j] = sb;
            outA[tok * (E_*NH_) + j] = sa;
        }
    }
}

// -------- causal depthwise conv (K=4) + SiLU; input row stride CS, C channels ---
__global__ void conv_silu_kernel(const float* __restrict__ xin, const float* __restrict__ w,
                                 float* __restrict__ out, int CS, int C)
{
    int c  = blockIdx.x * 256 + threadIdx.x;
    int b  = blockIdx.z;
    int l0 = blockIdx.y * 64;
    float w0 = w[c*4+0], w1 = w[c*4+1], w2 = w[c*4+2], w3 = w[c*4+3];
    const float* xb = xin + (long long)b * L_ * CS + c;
    float*       ob = out + (long long)b * L_ * C  + c;
    float xm3 = (l0 >= 3) ? xb[(long long)(l0-3)*CS] : 0.f;
    float xm2 = (l0 >= 2) ? xb[(long long)(l0-2)*CS] : 0.f;
    float xm1 = (l0 >= 1) ? xb[(long long)(l0-1)*CS] : 0.f;
    for (int l = l0; l < l0 + 64; ++l) {
        float x0 = xb[(long long)l*CS];
        float y  = w0*xm3 + w1*xm2 + w2*xm1 + w3*x0;
        ob[(long long)l*C] = y / (1.f + expf(-y));
        xm3 = xm2; xm2 = xm1; xm1 = x0;
    }
}

// ---------------- l2 normalize rows of 256 (optionally * scale) ----------------
__global__ void l2norm_kernel(float* __restrict__ data, float scale)
{
    int warp = threadIdx.x >> 5;
    int lane = threadIdx.x & 31;
    long long row = (long long)blockIdx.x * 8 + warp;
    float* p = data + row * HD_ + lane * 8;
    float4 a = *reinterpret_cast<float4*>(p);
    float4 b = *reinterpret_cast<float4*>(p + 4);
    float s = a.x*a.x + a.y*a.y + a.z*a.z + a.w*a.w
            + b.x*b.x + b.y*b.y + b.z*b.z + b.w*b.w;
#pragma unroll
    for (int off = 16; off; off >>= 1) s += __shfl_xor_sync(0xffffffffu, s, off);
    float r = rsqrtf(s + 1e-6f) * scale;
    a.x *= r; a.y *= r; a.z *= r; a.w *= r;
    b.x *= r; b.y *= r; b.z *= r; b.w *= r;
    *reinterpret_cast<float4*>(p)     = a;
    *reinterpret_cast<float4*>(p + 4) = b;
}

// ---------------- gating: decay and beta*mask per (e,b,h,t) --------------------
__global__ void gating_kernel(const float* __restrict__ betaA, const float* __restrict__ aA,
                              const int* __restrict__ mod, const float* __restrict__ A_log,
                              const float* __restrict__ dtb,
                              float* __restrict__ dec, float* __restrict__ bm)
{
    int idx = blockIdx.x * 256 + threadIdx.x;
    if (idx >= E_*B_*NH_*L_) return;
    int t = idx % L_;
    int h = (idx / L_) % NH_;
    int b = (idx / (L_*NH_)) % B_;
    int e = idx / (L_*NH_*B_);
    int tok = b * L_ + t;
    int j = e * NH_ + h;
    float braw = betaA[tok*(E_*NH_) + j];
    float beta = 1.f / (1.f + expf(-braw));
    float av = aA[tok*(E_*NH_) + j] + dtb[j];
    float sp = (av > 20.f) ? av : log1pf(expf(av));
    float g  = -expf(A_log[j]) * sp;
    int mid  = mod[tok];
    float m  = (e == 0) ? 1.f : ((e == 1) ? (mid == 0 ? 1.f : 0.f)
                                          : (mid == 1 ? 1.f : 0.f));
    dec[idx] = expf(g) * m + (1.f - m);
    bm[idx]  = beta * m;
}

// ---------------- zero fill -----------------------------------------------------
__global__ void zero_kernel(float4* __restrict__ p, int n4)
{
    int i = blockIdx.x * 256 + threadIdx.x;
    if (i < n4) p[i] = make_float4(0.f, 0.f, 0.f, 0.f);
}

// ---------------- recurrent scan: register state, v-partitioned, 1 sync/step ----
// masked steps (bm==0 <=> m==0 <=> dec==1 exactly): S unchanged, only o = q.S
__global__ __launch_bounds__(128) void scan_kernel(
    const float* __restrict__ qbuf, const float* __restrict__ kebuf,
    const float* __restrict__ vbuf, const float* __restrict__ decbuf,
    const float* __restrict__ bmbuf, const float* __restrict__ oww,
    float* __restrict__ opre)
{
    const int cta = blockIdx.x;
    const int vp = cta % NV_;
    const int h  = (cta / NV_) % NH_;
    const int b  = (cta / (NV_ * NH_)) % B_;
    const int e  = cta / (NV_ * NH_ * B_);
    const int tid = threadIdx.x;
    const int vl = tid >> 1;
    const int kh = tid & 1;
    const int vbase = vp * DVS_;

    float w0 = expf(oww[0*NH_ + h]);
    float w1 = expf(oww[1*NH_ + h]);
    float w2 = expf(oww[2*NH_ + h]);
    float wout = ((e == 0) ? w0 : ((e == 1) ? w1 : w2)) / (w0 + w1 + w2);

    __shared__ float ksm[2][264];
    __shared__ float qsm[2][264];

    float S[128];
#pragma unroll
    for (int j = 0; j < 128; j++) S[j] = 0.f;

    const float* decp = decbuf + ((e*B_ + b)*NH_ + h) * L_;
    const float* bmp  = bmbuf  + ((e*B_ + b)*NH_ + h) * L_;
    const float* kp   = kebuf + (long long)e * TOK_ * KD_ + (long long)b * L_ * KD_ + h * HD_;
    const float* qp   = qbuf  + (long long)b * L_ * KD_ + h * HD_;
    const float* vp_  = vbuf  + (long long)b * L_ * VD_ + h * DV_ + vbase + vl;
    float*       op   = opre  + (long long)b * L_ * VD_ + h * DV_ + vbase + vl;

    const int koff = kh * 132;
    const int idx4 = tid & 63;
    const int halfoff = ((idx4 >> 5) * 132) + ((idx4 * 4) & 127);
    const bool loadk = (tid < 64);
    const float* mysrc = loadk ? kp : qp;

    // preload t = 0
    {
        float4 v4 = *reinterpret_cast<const float4*>(mysrc + idx4 * 4);
        float* dst = loadk ? &ksm[0][0] : &qsm[0][0];
        *reinterpret_cast<float4*>(dst + halfoff) = v4;
    }
    float dec_c = decp[0], bm_c = bmp[0], v_c = vp_[0];
    __syncthreads();

    for (int t = 0; t < L_; ++t) {
        const int cur = t & 1;
        float dec_n = 0.f, bm_n = 0.f, v_n = 0.f;
        if (t + 1 < L_) {
            float4 v4 = *reinterpret_cast<const float4*>(mysrc + (long long)(t+1) * KD_ + idx4 * 4);
            float* dst = loadk ? &ksm[cur ^ 1][0] : &qsm[cur ^ 1][0];
            *reinterpret_cast<float4*>(dst + halfoff) = v4;
            dec_n = decp[t+1]; bm_n = bmp[t+1]; v_n = vp_[(long long)(t+1) * VD_];
        }
        const float* kb = &ksm[cur][koff];
        const float* qb = &qsm[cur][koff];
        float o;

        if (bm_c != 0.f) {
            // pass 1: decay + predicted value
            float p0 = 0.f, p1 = 0.f, p2 = 0.f, p3 = 0.f;
#pragma unroll
            for (int j = 0; j < 128; j += 4) {
                float4 kv = *reinterpret_cast<const float4*>(&kb[j]);
                S[j+0] *= dec_c; p0 += kv.x * S[j+0];
                S[j+1] *= dec_c; p1 += kv.y * S[j+1];
                S[j+2] *= dec_c; p2 += kv.z * S[j+2];
                S[j+3] *= dec_c; p3 += kv.w * S[j+3];
            }
            float pred = (p0 + p1) + (p2 + p3);
            pred += __shfl_xor_sync(0xffffffffu, pred, 1);
            float delta = (v_c - pred) * bm_c;

            // pass 2: rank-1 update + output
            float o0 = 0.f, o1 = 0.f, o2 = 0.f, o3 = 0.f;
#pragma unroll
            for (int j = 0; j < 128; j += 4) {
                float4 kv = *reinterpret_cast<const float4*>(&kb[j]);
                float4 qv = *reinterpret_cast<const float4*>(&qb[j]);
                S[j+0] += kv.x * delta; o0 += qv.x * S[j+0];
                S[j+1] += kv.y * delta; o1 += qv.y * S[j+1];
                S[j+2] += kv.z * delta; o2 += qv.z * S[j+2];
                S[j+3] += kv.w * delta; o3 += qv.w * S[j+3];
            }
            o = (o0 + o1) + (o2 + o3);
        } else {
            // masked step: dec==1 and delta==0 -> S unchanged, output only
            float o0 = 0.f, o1 = 0.f, o2 = 0.f, o3 = 0.f;
#pragma unroll
            for (int j = 0; j < 128; j += 4) {
                float4 qv = *reinterpret_cast<const float4*>(&qb[j]);
                o0 += qv.x * S[j+0];
                o1 += qv.y * S[j+1];
                o2 += qv.z * S[j+2];
                o3 += qv.w * S[j+3];
            }
            o = (o0 + o1) + (o2 + o3);
        }
        o += __shfl_xor_sync(0xffffffffu, o, 1);
        if (kh == 0) atomicAdd(&op[(long long)t * VD_], o * wout);

        __syncthreads();
        dec_c = dec_n; bm_c = bm_n; v_c = v_n;
    }
}

// -------- RMSNorm * weight * SiLU(gate), emitting split-bf16 A-operand ----------
// gate lives in xvg[tok][VD_ + h*DV_ + i] (row stride 2*VD_)
__global__ __launch_bounds__(128) void norm_gate_kernel(
    const float* __restrict__ opre, const float* __restrict__ xvg,
    const float* __restrict__ wnorm, __nv_bfloat16* __restrict__ out3)
{
    int row = blockIdx.x;                       // tok*NH + h
    int tok = row >> 3;
    int hh  = row & 7;
    long long base = (long long)row * DV_;      // opre: [tok][VD] contiguous
    const float* o = opre + base;
    const float* g = xvg + (long long)tok * (2*VD_) + VD_ + hh * DV_;
    int i = threadIdx.x * 4;
    float4 ov = *reinterpret_cast<const float4*>(&o[i]);
    float ss = ov.x*ov.x + ov.y*ov.y + ov.z*ov.z + ov.w*ov.w;
#pragma unroll
    for (int off = 16; off; off >>= 1) ss += __shfl_xor_sync(0xffffffffu, ss, off);
    __shared__ float red[4];
    int warp = threadIdx.x >> 5, lane = threadIdx.x & 31;
    if (lane == 0) red[warp] = ss;
    __syncthreads();
    float tot = red[0] + red[1] + red[2] + red[3];
    float inv = rsqrtf(tot * (1.f / (float)DV_) + 1e-5f);
    float4 wv = *reinterpret_cast<const float4*>(&wnorm[i]);
    float4 gv = *reinterpret_cast<const float4*>(&g[i]);
    float r[4];
    r[0] = ov.x * inv * wv.x * (gv.x / (1.f + expf(-gv.x)));
    r[1] = ov.y * inv * wv.y * (gv.y / (1.f + expf(-gv.y)));
    r[2] = ov.z * inv * wv.z * (gv.z / (1.f + expf(-gv.z)));
    r[3] = ov.w * inv * wv.w * (gv.w / (1.f + expf(-gv.w)));
    int col = hh * DV_ + i;
    long long b3 = (long long)tok * (3LL * VD_) + col;
#pragma unroll
    for (int j = 0; j < 4; ++j) {
        __nv_bfloat16 hb = __float2bfloat16(r[j]);
        __nv_bfloat16 lb = __float2bfloat16(r[j] - __bfloat162float(hb));
        out3[b3 + j]            = hb;
        out3[b3 + VD_ + j]      = lb;
        out3[b3 + 2LL*VD_ + j]  = hb;
    }
}

// ================================ launch ======================================
extern "C" void kernel_launch(void* const* d_in, const int* in_sizes, int n_in,
                              void* d_out, int out_size)
{
    const float* X    = (const float*)d_in[0];
    const int*   mod  = (const int*)  d_in[1];
    const float* Wq   = (const float*)d_in[2];
    const float* Wk   = (const float*)d_in[3];
    const float* Wv   = (const float*)d_in[4];
    const float* cq   = (const float*)d_in[5];
    const float* ck   = (const float*)d_in[6];
    const float* cv   = (const float*)d_in[7];
    const float* Wek  = (const float*)d_in[8];
    const float* Wb   = (const float*)d_in[9];
    const float* Wa   = (const float*)d_in[10];
    const float* Alog = (const float*)d_in[11];
    const float* dtb  = (const float*)d_in[12];
    const float* ow   = (const float*)d_in[13];
    const float* Wg   = (const float*)d_in[14];
    const float* onw  = (const float*)d_in[15];
    const float* Wo   = (const float*)d_in[16];
    float* out = (float*)d_out;

    float *xqk, *xvg, *q, *k, *v, *ke, *ba, *aa, *dec, *bm, *opre;
    __nv_bfloat16 *X3, *Wqk3, *Wvg3, *Wo3, *of3;
    cudaGetSymbolAddress((void**)&xqk,  g_xqk);
    cudaGetSymbolAddress((void**)&xvg,  g_xvg);
    cudaGetSymbolAddress((void**)&q,    g_q);
    cudaGetSymbolAddress((void**)&k,    g_k);
    cudaGetSymbolAddress((void**)&v,    g_v);
    cudaGetSymbolAddress((void**)&ke,   g_ke);
    cudaGetSymbolAddress((void**)&ba,   g_betaA);
    cudaGetSymbolAddress((void**)&aa,   g_aA);
    cudaGetSymbolAddress((void**)&dec,  g_dec);
    cudaGetSymbolAddress((void**)&bm,   g_bm);
    cudaGetSymbolAddress((void**)&opre, g_opre);
    cudaGetSymbolAddress((void**)&X3,   g_X3);
    cudaGetSymbolAddress((void**)&Wqk3, g_Wqk3);
    cudaGetSymbolAddress((void**)&Wvg3, g_Wvg3);
    cudaGetSymbolAddress((void**)&Wo3,  g_Wo3);
    cudaGetSymbolAddress((void**)&of3,  g_of3);

    // split fp32 -> bf16 triples (combined weight buffers)
    split3_kernel<<<TOK_*HS_/256, 256>>>(X,  X3,  HS_, 1);
    split3_kernel<<<KD_*HS_/256, 256>>>(Wq, Wqk3,                        HS_, 0);
    split3_kernel<<<KD_*HS_/256, 256>>>(Wk, Wqk3 + (long long)KD_*3*HS_, HS_, 0);
    split3_kernel<<<VD_*HS_/256, 256>>>(Wv, Wvg3,                        HS_, 0);
    split3_kernel<<<VD_*HS_/256, 256>>>(Wg, Wvg3 + (long long)VD_*3*HS_, HS_, 0);
    split3_kernel<<<HS_*VD_/256, 256>>>(Wo, Wo3, VD_, 0);

    // merged projections on HMMA tensor cores (K3 = 3*HS = 6144)
    hmma_gemm<<<dim3((2*KD_)/128, TOK_/128), 256>>>(X3, Wqk3, xqk, 3*HS_, 2*KD_);
    hmma_gemm<<<dim3((2*VD_)/128, TOK_/128), 256>>>(X3, Wvg3, xvg, 3*HS_, 2*VD_);
    proj_ba_kernel<<<TOK_, 256>>>(X, Wb, Wa, ba, aa);

    // causal conv + SiLU (inputs strided inside combined buffers)
    conv_silu_kernel<<<dim3(KD_/256, L_/64, B_), 256>>>(xqk,        cq, q, 2*KD_, KD_);
    conv_silu_kernel<<<dim3(KD_/256, L_/64, B_), 256>>>(xqk + KD_,  ck, k, 2*KD_, KD_);
    conv_silu_kernel<<<dim3(VD_/256, L_/64, B_), 256>>>(xvg,        cv, v, 2*VD_, VD_);

    // l2 norm per head row; q additionally scaled by HD^-0.5
    l2norm_kernel<<<TOK_*NH_/8, 256>>>(q, 0.0625f);
    l2norm_kernel<<<TOK_*NH_/8, 256>>>(k, 1.0f);

    // per-expert per-head key transform (small, stays fp32)
    for (int e = 0; e < E_; ++e) {
        sgemm_nt<<<dim3(2,16,8), 256>>>(
            k, Wek + (long long)e * NH_ * HD_ * HD_, ke + (long long)e * TOK_ * KD_,
            TOK_, HD_, HD_, KD_, HD_, KD_,
            (long long)HD_, (long long)HD_ * HD_, (long long)HD_);
    }

    // gating scalars
    gating_kernel<<<(E_*B_*NH_*L_ + 255)/256, 256>>>(ba, aa, mod, Alog, dtb, dec, bm);

    // zero the expert-aggregated output accumulator
    zero_kernel<<<(TOK_*VD_/4 + 255)/256, 256>>>((float4*)opre, TOK_*VD_/4);

    // the sequential scan (scalar state + masked-step fast path)
    scan_kernel<<<E_*B_*NH_*NV_, 128>>>(q, ke, v, dec, bm, ow, opre);

    // RMSNorm + swish gate -> split-bf16 A operand
    norm_gate_kernel<<<TOK_*NH_, 128>>>(opre, xvg, onw, of3);

    // output projection on HMMA tensor cores (K3 = 3*VD = 12288)
    hmma_gemm<<<dim3(HS_/128, TOK_/128), 256>>>(of3, Wo3, out, 3*VD_, HS_);
}

// round 9
// speedup vs baseline: 2.2370x; 1.0161x over previous
#include <cuda_runtime.h>
#include <cuda_bf16.h>
#include <cstdint>
#include <math.h>

#define B_   2
#define L_   1024
#define HS_  2048
#define NH_  8
#define HD_  256
#define DV_  512
#define KD_  2048
#define VD_  4096
#define E_   3
#define TOK_ 2048
#define NV_  8
#define DVS_ 64

// ---------------- scratch (static device arrays; no allocation) ----------------
__device__ __align__(16) float g_xqk[TOK_*(2*KD_)];   // [tok][q|k]  stride 4096
__device__ __align__(16) float g_xvg[TOK_*(2*VD_)];   // [tok][v|g]  stride 8192
__device__ __align__(16) float g_q [TOK_*KD_];
__device__ __align__(16) float g_k [TOK_*KD_];
__device__ __align__(16) float g_v [TOK_*VD_];
__device__ __align__(16) float g_ke[E_*TOK_*KD_];
__device__ __align__(16) float g_betaA[TOK_*E_*NH_];
__device__ __align__(16) float g_aA  [TOK_*E_*NH_];
__device__ __align__(16) float g_dec [E_*B_*NH_*L_];
__device__ __align__(16) float g_bm  [E_*B_*NH_*L_];
__device__ __align__(16) float g_opre[TOK_*VD_];

// split-bf16 buffers: A-side layout [hi | lo | hi], B-side layout [hi | hi | lo]
__device__ __align__(16) __nv_bfloat16 g_X3  [TOK_*3*HS_];
__device__ __align__(16) __nv_bfloat16 g_Wqk3[(2*KD_)*3*HS_];
__device__ __align__(16) __nv_bfloat16 g_Wvg3[(2*VD_)*3*HS_];
__device__ __align__(16) __nv_bfloat16 g_Wo3 [HS_*3*VD_];
__device__ __align__(16) __nv_bfloat16 g_of3 [TOK_*3*VD_];
__device__ __align__(16) __nv_bfloat16 g_k3  [NH_*TOK_*3*HD_];      // per-head A operand
__device__ __align__(16) __nv_bfloat16 g_Wek3[E_*NH_*HD_*3*HD_];    // per-(e,h) B operand

// ======================= helpers =============================================
__device__ __forceinline__ void cp16(uint32_t dst, const void* src) {
    asm volatile("cp.async.cg.shared.global [%0], [%1], 16;" :: "r"(dst), "l"(src));
}
#define CP_COMMIT() asm volatile("cp.async.commit_group;" ::: "memory")
#define CP_WAIT(n)  asm volatile("cp.async.wait_group %0;" :: "n"(n) : "memory")

#define MMA16816(d, a0, a1, a2, a3, b0, b1) \
    asm volatile("mma.sync.aligned.m16n8k16.row.col.f32.bf16.bf16.f32 " \
                 "{%0,%1,%2,%3}, {%4,%5,%6,%7}, {%8,%9}, {%0,%1,%2,%3};" \
                 : "+f"((d)[0]), "+f"((d)[1]), "+f"((d)[2]), "+f"((d)[3]) \
                 : "r"(a0), "r"(a1), "r"(a2), "r"(a3), "r"(b0), "r"(b1))

// packed f32x2 (Blackwell)
typedef unsigned long long u64;
__device__ __forceinline__ u64 pack2(float x, float y) {
    u64 r; asm("mov.b64 %0, {%1, %2};" : "=l"(r) : "f"(x), "f"(y)); return r;
}
__device__ __forceinline__ float2 unpack2(u64 v) {
    float2 f; asm("mov.b64 {%0, %1}, %2;" : "=f"(f.x), "=f"(f.y) : "l"(v)); return f;
}
#define FMA2(d, a, b, c) \
    asm("fma.rn.f32x2 %0, %1, %2, %3;" : "=l"(d) : "l"(a), "l"(b), "l"(c))
#define MUL2(d, a, b) \
    asm("mul.rn.f32x2 %0, %1, %2;" : "=l"(d) : "l"(a), "l"(b))

// ============== HMMA split-bf16 GEMM: C[M,N] = A3[M,K3] * B3[N,K3]^T ===========
// tile 128x128, BK=32, 256 threads (8 warps, 2x4), double-buffered cp.async.
// smem row stride 40 bf16 (80B) -> conflict-free quad-pattern LDS.32.
#define BKC 32
#define SROW 40
#define STILE (128 * SROW)   // elements per operand tile

struct HmmaCore {
    __device__ __forceinline__ static void run(
        const __nv_bfloat16* gAbase, const __nv_bfloat16* gBbase,
        float* C, int K3, int ldc, int bm, int bn,
        __nv_bfloat16 (*sm)[2][STILE])
    {
        const int tid = threadIdx.x;
        const int lane = tid & 31, wid = tid >> 5;
        const int wm = wid >> 2;
        const int wn = wid & 3;
        const int grp = lane >> 2;
        const int qd  = lane & 3;
        const uint32_t sbase = (uint32_t)__cvta_generic_to_shared(&sm[0][0][0]);
        const int NC = K3 / BKC;

        const int lrow = tid >> 1;
        const int lch2 = (tid & 1) * 2;
        const __nv_bfloat16* gA = gAbase + (long long)(bm + lrow) * K3 + lch2 * 8;
        const __nv_bfloat16* gB = gBbase + (long long)(bn + lrow) * K3 + lch2 * 8;
        const uint32_t sA0 = sbase + (uint32_t)(lrow * SROW + lch2 * 8) * 2;
        const uint32_t sB0 = sA0 + (uint32_t)STILE * 2;

        auto load_chunk = [&](int c, int s) {
            uint32_t off = (uint32_t)(s * 2 * STILE) * 2;
            const __nv_bfloat16* pa = gA + (long long)c * BKC;
            const __nv_bfloat16* pb = gB + (long long)c * BKC;
            cp16(sA0 + off,      pa);
            cp16(sA0 + off + 16, pa + 8);
            cp16(sB0 + off,      pb);
            cp16(sB0 + off + 16, pb + 8);
            CP_COMMIT();
        };

        float acc[4][4][4];
#pragma unroll
        for (int i = 0; i < 4; i++)
#pragma unroll
            for (int j = 0; j < 4; j++)
#pragma unroll
                for (int r = 0; r < 4; r++) acc[i][j][r] = 0.f;

        load_chunk(0, 0);
        int s = 0;
        for (int c = 0; c < NC; ++c) {
            if (c + 1 < NC) { load_chunk(c + 1, s ^ 1); CP_WAIT(1); }
            else           { CP_WAIT(0); }
            __syncthreads();

            const uint32_t* Ab = reinterpret_cast<const uint32_t*>(sm[s][0]);
            const uint32_t* Bb = reinterpret_cast<const uint32_t*>(sm[s][1]);
#pragma unroll
            for (int kk = 0; kk < 2; ++kk) {
                const int kof = kk * 16 + qd * 2;
                uint32_t af[4][4];
#pragma unroll
                for (int mt = 0; mt < 4; ++mt) {
                    int r0 = wm * 64 + mt * 16 + grp;
                    const uint32_t* p = Ab + ((r0 * SROW + kof) >> 1);
                    af[mt][0] = p[0];
                    af[mt][1] = p[(8 * SROW) >> 1];
                    af[mt][2] = p[4];
                    af[mt][3] = p[((8 * SROW) >> 1) + 4];
                }
                uint32_t bf[4][2];
#pragma unroll
                for (int nt = 0; nt < 4; ++nt) {
                    int r0 = wn * 32 + nt * 8 + grp;
                    const uint32_t* p = Bb + ((r0 * SROW + kof) >> 1);
                    bf[nt][0] = p[0];
                    bf[nt][1] = p[4];
                }
#pragma unroll
                for (int mt = 0; mt < 4; ++mt)
#pragma unroll
                    for (int nt = 0; nt < 4; ++nt)
                        MMA16816(acc[mt][nt], af[mt][0], af[mt][1], af[mt][2], af[mt][3],
                                 bf[nt][0], bf[nt][1]);
            }
            __syncthreads();
            s ^= 1;
        }

#pragma unroll
        for (int mt = 0; mt < 4; ++mt) {
            int row0 = bm + wm * 64 + mt * 16 + grp;
#pragma unroll
            for (int nt = 0; nt < 4; ++nt) {
                int col = bn + wn * 32 + nt * 8 + qd * 2;
                *reinterpret_cast<float2*>(&C[(long long)row0 * ldc + col]) =
                    make_float2(acc[mt][nt][0], acc[mt][nt][1]);
                *reinterpret_cast<float2*>(&C[(long long)(row0 + 8) * ldc + col]) =
                    make_float2(acc[mt][nt][2], acc[mt][nt][3]);
            }
        }
    }
};

__global__ __launch_bounds__(256) void hmma_gemm(
    const __nv_bfloat16* __restrict__ A, const __nv_bfloat16* __restrict__ B,
    float* __restrict__ C, int K3, int ldc)
{
    __shared__ __nv_bfloat16 sm[2][2][STILE];
    HmmaCore::run(A, B, C, K3, ldc, blockIdx.y * 128, blockIdx.x * 128, sm);
}

// batched over z = e*NH + h: ke[e][tok][h*HD + :] = k3[h] @ Wek3[e,h]^T
__global__ __launch_bounds__(256) void hmma_gemm_ke(
    const __nv_bfloat16* __restrict__ k3, const __nv_bfloat16* __restrict__ Wek3,
    float* __restrict__ ke)
{
    __shared__ __nv_bfloat16 sm[2][2][STILE];
    const int z = blockIdx.z;
    const int e = z >> 3, h = z & 7;
    const __nv_bfloat16* A = k3  + (long long)h * TOK_ * (3*HD_);
    const __nv_bfloat16* B = Wek3 + (long long)z * HD_ * (3*HD_);
    float* C = ke + (long long)e * TOK_ * KD_ + h * HD_;
    HmmaCore::run(A, B, C, 3*HD_, KD_, blockIdx.y * 128, blockIdx.x * 128, sm);
}

// ---------------- fp32 -> split-bf16 triple layout ------------------------------
// aSide=1 -> [h | l | h] (A operand);  aSide=0 -> [h | h | l] (B operand)
__global__ void split3_kernel(const float* __restrict__ src, __nv_bfloat16* __restrict__ dst,
                              int K, int aSide)
{
    long long i = (long long)blockIdx.x * 256 + threadIdx.x;
    int row = (int)(i / K);
    int col = (int)(i - (long long)row * K);
    float x = src[i];
    __nv_bfloat16 h = __float2bfloat16(x);
    __nv_bfloat16 l = __float2bfloat16(x - __bfloat162float(h));
    long long b = (long long)row * (3LL * K) + col;
    dst[b] = h;
    dst[b + K]     = aSide ? l : h;
    dst[b + 2LL*K] = aSide ? h : l;
}

// k [TOK][KD] fp32 -> k3 [NH][TOK][3*HD] split-bf16 A-side
__global__ void split3_k_kernel(const float* __restrict__ k, __nv_bfloat16* __restrict__ k3)
{
    long long i = (long long)blockIdx.x * 256 + threadIdx.x;   // over TOK*KD
    int tok = (int)(i / KD_);
    int rem = (int)(i - (long long)tok * KD_);
    int h = rem >> 8;            // / HD_
    int d = rem & 255;           // % HD_
    float x = k[i];
    __nv_bfloat16 hi = __float2bfloat16(x);
    __nv_bfloat16 lo = __float2bfloat16(x - __bfloat162float(hi));
    long long b = ((long long)h * TOK_ + tok) * (3LL*HD_) + d;
    k3[b]           = hi;
    k3[b + HD_]     = lo;
    k3[b + 2*HD_]   = hi;
}

// ------------- small projection: beta_raw / a_raw = X @ {Wb,Wa}^T ---------------
__global__ __launch_bounds__(256) void proj_ba_kernel(
    const float* __restrict__ X, const float* __restrict__ Wb, const float* __restrict__ Wa,
    float* __restrict__ outB, float* __restrict__ outA)
{
    __shared__ float xs[HS_];
    int tok = blockIdx.x;
    const float* xr = X + (long long)tok * HS_;
    for (int i = threadIdx.x * 4; i < HS_; i += 256 * 4)
        *reinterpret_cast<float4*>(&xs[i]) = *reinterpret_cast<const float4*>(&xr[i]);
    __syncthreads();
    int warp = threadIdx.x >> 5, lane = threadIdx.x & 31;
    for (int j = warp; j < E_ * NH_; j += 8) {
        const float* wb = Wb + (long long)j * HS_;
        const float* wa = Wa + (long long)j * HS_;
        float sb = 0.f, sa = 0.f;
        for (int i = lane * 4; i < HS_; i += 32 * 4) {
            float4 xv = *reinterpret_cast<const float4*>(&xs[i]);
            float4 bv = *reinterpret_cast<const float4*>(&wb[i]);
            float4 av = *reinterpret_cast<const float4*>(&wa[i]);
            sb += xv.x*bv.x + xv.y*bv.y + xv.z*bv.z + xv.w*bv.w;
            sa += xv.x*av.x + xv.y*av.y + xv.z*av.z + xv.w*av.w;
        }
#pragma unroll
        for (int off = 16; off; off >>= 1) {
            sb += __shfl_xor_sync(0xffffffffu, sb, off);
            sa += __shfl_xor_sync(0xffffffffu, sa, off);
        }
        if (lane == 0) {
            outB[tok * (E_*NH_) + j] = sb;
            outA[tok * (E_*NH_) + j] = sa;
        }
    }
}

// -------- causal depthwise conv (K=4) + SiLU; input row stride CS, C channels ---
__global__ void conv_silu_kernel(const float* __restrict__ xin, const float* __restrict__ w,
                                 float* __restrict__ out, int CS, int C)
{
    int c  = blockIdx.x * 256 + threadIdx.x;
    int b  = blockIdx.z;
    int l0 = blockIdx.y * 64;
    float w0 = w[c*4+0], w1 = w[c*4+1], w2 = w[c*4+2], w3 = w[c*4+3];
    const float* xb = xin + (long long)b * L_ * CS + c;
    float*       ob = out + (long long)b * L_ * C  + c;
    float xm3 = (l0 >= 3) ? xb[(long long)(l0-3)*CS] : 0.f;
    float xm2 = (l0 >= 2) ? xb[(long long)(l0-2)*CS] : 0.f;
    float xm1 = (l0 >= 1) ? xb[(long long)(l0-1)*CS] : 0.f;
    for (int l = l0; l < l0 + 64; ++l) {
        float x0 = xb[(long long)l*CS];
        float y  = w0*xm3 + w1*xm2 + w2*xm1 + w3*x0;
        ob[(long long)l*C] = y / (1.f + expf(-y));
        xm3 = xm2; xm2 = xm1; xm1 = x0;
    }
}

// ---------------- l2 normalize rows of 256 (optionally * scale) ----------------
__global__ void l2norm_kernel(float* __restrict__ data, float scale)
{
    int warp = threadIdx.x >> 5;
    int lane = threadIdx.x & 31;
    long long row = (long long)blockIdx.x * 8 + warp;
    float* p = data + row * HD_ + lane * 8;
    float4 a = *reinterpret_cast<float4*>(p);
    float4 b = *reinterpret_cast<float4*>(p + 4);
    float s = a.x*a.x + a.y*a.y + a.z*a.z + a.w*a.w
            + b.x*b.x + b.y*b.y + b.z*b.z + b.w*b.w;
#pragma unroll
    for (int off = 16; off; off >>= 1) s += __shfl_xor_sync(0xffffffffu, s, off);
    float r = rsqrtf(s + 1e-6f) * scale;
    a.x *= r; a.y *= r; a.z *= r; a.w *= r;
    b.x *= r; b.y *= r; b.z *= r; b.w *= r;
    *reinterpret_cast<float4*>(p)     = a;
    *reinterpret_cast<float4*>(p + 4) = b;
}

// ---------------- gating: decay and beta*mask per (e,b,h,t) --------------------
__global__ void gating_kernel(const float* __restrict__ betaA, const float* __restrict__ aA,
                              const int* __restrict__ mod, const float* __restrict__ A_log,
                              const float* __restrict__ dtb,
                              float* __restrict__ dec, float* __restrict__ bm)
{
    int idx = blockIdx.x * 256 + threadIdx.x;
    if (idx >= E_*B_*NH_*L_) return;
    int t = idx % L_;
    int h = (idx / L_) % NH_;
    int b = (idx / (L_*NH_)) % B_;
    int e = idx / (L_*NH_*B_);
    int tok = b * L_ + t;
    int j = e * NH_ + h;
    float braw = betaA[tok*(E_*NH_) + j];
    float beta = 1.f / (1.f + expf(-braw));
    float av = aA[tok*(E_*NH_) + j] + dtb[j];
    float sp = (av > 20.f) ? av : log1pf(expf(av));
    float g  = -expf(A_log[j]) * sp;
    int mid  = mod[tok];
    float m  = (e == 0) ? 1.f : ((e == 1) ? (mid == 0 ? 1.f : 0.f)
                                          : (mid == 1 ? 1.f : 0.f));
    dec[idx] = expf(g) * m + (1.f - m);
    bm[idx]  = beta * m;
}

// ---------------- zero fill -----------------------------------------------------
__global__ void zero_kernel(float4* __restrict__ p, int n4)
{
    int i = blockIdx.x * 256 + threadIdx.x;
    if (i < n4) p[i] = make_float4(0.f, 0.f, 0.f, 0.f);
}

// ------- recurrent scan: packed f32x2 state, v-partitioned, 1 sync/step ---------
// NO min-blocks clamp (R7 lesson: forcing 3 CTAs/SM spilled the state array).
// masked steps (bm==0 <=> dec==1 exactly): S unchanged, output only.
__global__ __launch_bounds__(128) void scan_kernel(
    const float* __restrict__ qbuf, const float* __restrict__ kebuf,
    const float* __restrict__ vbuf, const float* __restrict__ decbuf,
    const float* __restrict__ bmbuf, const float* __restrict__ oww,
    float* __restrict__ opre)
{
    const int cta = blockIdx.x;
    const int vp = cta % NV_;
    const int h  = (cta / NV_) % NH_;
    const int b  = (cta / (NV_ * NH_)) % B_;
    const int e  = cta / (NV_ * NH_ * B_);
    const int tid = threadIdx.x;
    const int vl = tid >> 1;
    const int kh = tid & 1;
    const int vbase = vp * DVS_;

    float w0 = expf(oww[0*NH_ + h]);
    float w1 = expf(oww[1*NH_ + h]);
    float w2 = expf(oww[2*NH_ + h]);
    float wout = ((e == 0) ? w0 : ((e == 1) ? w1 : w2)) / (w0 + w1 + w2);

    __shared__ __align__(16) float ksm[2][264];
    __shared__ __align__(16) float qsm[2][264];

    u64 S2[64];
    const u64 z2 = pack2(0.f, 0.f);
#pragma unroll
    for (int j = 0; j < 64; j++) S2[j] = z2;

    const float* decp = decbuf + ((e*B_ + b)*NH_ + h) * L_;
    const float* bmp  = bmbuf  + ((e*B_ + b)*NH_ + h) * L_;
    const float* kp   = kebuf + (long long)e * TOK_ * KD_ + (long long)b * L_ * KD_ + h * HD_;
    const float* qp   = qbuf  + (long long)b * L_ * KD_ + h * HD_;
    const float* vp_  = vbuf  + (long long)b * L_ * VD_ + h * DV_ + vbase + vl;
    float*       op   = opre  + (long long)b * L_ * VD_ + h * DV_ + vbase + vl;

    const int koff = kh * 132;          // 528 B, 16B aligned
    const int idx4 = tid & 63;
    const int halfoff = ((idx4 >> 5) * 132) + ((idx4 * 4) & 127);
    const bool loadk = (tid < 64);
    const float* mysrc = loadk ? kp : qp;

    // preload t = 0
    {
        float4 v4 = *reinterpret_cast<const float4*>(mysrc + idx4 * 4);
        float* dst = loadk ? &ksm[0][0] : &qsm[0][0];
        *reinterpret_cast<float4*>(dst + halfoff) = v4;
    }
    float dec_c = decp[0], bm_c = bmp[0], v_c = vp_[0];
    __syncthreads();

    for (int t = 0; t < L_; ++t) {
        const int cur = t & 1;
        float dec_n = 0.f, bm_n = 0.f, v_n = 0.f;
        if (t + 1 < L_) {
            float4 v4 = *reinterpret_cast<const float4*>(mysrc + (long long)(t+1) * KD_ + idx4 * 4);
            float* dst = loadk ? &ksm[cur ^ 1][0] : &qsm[cur ^ 1][0];
            *reinterpret_cast<float4*>(dst + halfoff) = v4;
            dec_n = decp[t+1]; bm_n = bmp[t+1]; v_n = vp_[(long long)(t+1) * VD_];
        }
        const float* kb = &ksm[cur][koff];
        const float* qb = &qsm[cur][koff];
        float o;

        if (bm_c != 0.f) {
            // pass 1: decay + predicted value
            const u64 dd = pack2(dec_c, dec_c);
            u64 a0 = z2, a1 = z2;
#pragma unroll
            for (int j = 0; j < 128; j += 4) {
                ulonglong2 kk = *reinterpret_cast<const ulonglong2*>(kb + j);
                const int i = j >> 1;
                MUL2(S2[i],   S2[i],   dd);
                FMA2(a0, kk.x, S2[i],   a0);
                MUL2(S2[i+1], S2[i+1], dd);
                FMA2(a1, kk.y, S2[i+1], a1);
            }
            float2 f0 = unpack2(a0), f1 = unpack2(a1);
            float pred = (f0.x + f0.y) + (f1.x + f1.y);
            pred += __shfl_xor_sync(0xffffffffu, pred, 1);
            float delta = (v_c - pred) * bm_c;
            const u64 del2 = pack2(delta, delta);

            // pass 2: rank-1 update + output
            u64 b0 = z2, b1 = z2;
#pragma unroll
            for (int j = 0; j < 128; j += 4) {
                ulonglong2 kk = *reinterpret_cast<const ulonglong2*>(kb + j);
                ulonglong2 qq = *reinterpret_cast<const ulonglong2*>(qb + j);
                const int i = j >> 1;
                FMA2(S2[i],   kk.x, del2, S2[i]);
                FMA2(b0, qq.x, S2[i],   b0);
                FMA2(S2[i+1], kk.y, del2, S2[i+1]);
                FMA2(b1, qq.y, S2[i+1], b1);
            }
            float2 g0 = unpack2(b0), g1 = unpack2(b1);
            o = (g0.x + g0.y) + (g1.x + g1.y);
        } else {
            // masked step: S unchanged, output only
            u64 b0 = z2, b1 = z2;
#pragma unroll
            for (int j = 0; j < 128; j += 4) {
                ulonglong2 qq = *reinterpret_cast<const ulonglong2*>(qb + j);
                const int i = j >> 1;
                FMA2(b0, qq.x, S2[i],   b0);
                FMA2(b1, qq.y, S2[i+1], b1);
            }
            float2 g0 = unpack2(b0), g1 = unpack2(b1);
            o = (g0.x + g0.y) + (g1.x + g1.y);
        }
        o += __shfl_xor_sync(0xffffffffu, o, 1);
        if (kh == 0) atomicAdd(&op[(long long)t * VD_], o * wout);

        __syncthreads();
        dec_c = dec_n; bm_c = bm_n; v_c = v_n;
    }
}

// -------- RMSNorm * weight * SiLU(gate), emitting split-bf16 A-operand ----------
// gate lives in xvg[tok][VD_ + h*DV_ + i] (row stride 2*VD_)
__global__ __launch_bounds__(128) void norm_gate_kernel(
    const float* __restrict__ opre, const float* __restrict__ xvg,
    const float* __restrict__ wnorm, __nv_bfloat16* __restrict__ out3)
{
    int row = blockIdx.x;                       // tok*NH + h
    int tok = row >> 3;
    int hh  = row & 7;
    long long base = (long long)row * DV_;
    const float* o = opre + base;
    const float* g = xvg + (long long)tok * (2*VD_) + VD_ + hh * DV_;
    int i = threadIdx.x * 4;
    float4 ov = *reinterpret_cast<const float4*>(&o[i]);
    float ss = ov.x*ov.x + ov.y*ov.y + ov.z*ov.z + ov.w*ov.w;
#pragma unroll
    for (int off = 16; off; off >>= 1) ss += __shfl_xor_sync(0xffffffffu, ss, off);
    __shared__ float red[4];
    int warp = threadIdx.x >> 5, lane = threadIdx.x & 31;
    if (lane == 0) red[warp] = ss;
    __syncthreads();
    float tot = red[0] + red[1] + red[2] + red[3];
    float inv = rsqrtf(tot * (1.f / (float)DV_) + 1e-5f);
    float4 wv = *reinterpret_cast<const float4*>(&wnorm[i]);
    float4 gv = *reinterpret_cast<const float4*>(&g[i]);
    float r[4];
    r[0] = ov.x * inv * wv.x * (gv.x / (1.f + expf(-gv.x)));
    r[1] = ov.y * inv * wv.y * (gv.y / (1.f + expf(-gv.y)));
    r[2] = ov.z * inv * wv.z * (gv.z / (1.f + expf(-gv.z)));
    r[3] = ov.w * inv * wv.w * (gv.w / (1.f + expf(-gv.w)));
    int col = hh * DV_ + i;
    long long b3 = (long long)tok * (3LL * VD_) + col;
#pragma unroll
    for (int j = 0; j < 4; ++j) {
        __nv_bfloat16 hb = __float2bfloat16(r[j]);
        __nv_bfloat16 lb = __float2bfloat16(r[j] - __bfloat162float(hb));
        out3[b3 + j]            = hb;
        out3[b3 + VD_ + j]      = lb;
        out3[b3 + 2LL*VD_ + j]  = hb;
    }
}

// ================================ launch ======================================
extern "C" void kernel_launch(void* const* d_in, const int* in_sizes, int n_in,
                              void* d_out, int out_size)
{
    const float* X    = (const float*)d_in[0];
    const int*   mod  = (const int*)  d_in[1];
    const float* Wq   = (const float*)d_in[2];
    const float* Wk   = (const float*)d_in[3];
    const float* Wv   = (const float*)d_in[4];
    const float* cq   = (const float*)d_in[5];
    const float* ck   = (const float*)d_in[6];
    const float* cv   = (const float*)d_in[7];
    const float* Wek  = (const float*)d_in[8];
    const float* Wb   = (const float*)d_in[9];
    const float* Wa   = (const float*)d_in[10];
    const float* Alog = (const float*)d_in[11];
    const float* dtb  = (const float*)d_in[12];
    const float* ow   = (const float*)d_in[13];
    const float* Wg   = (const float*)d_in[14];
    const float* onw  = (const float*)d_in[15];
    const float* Wo   = (const float*)d_in[16];
    float* out = (float*)d_out;

    float *xqk, *xvg, *q, *k, *v, *ke, *ba, *aa, *dec, *bm, *opre;
    __nv_bfloat16 *X3, *Wqk3, *Wvg3, *Wo3, *of3, *k3, *Wek3;
    cudaGetSymbolAddress((void**)&xqk,  g_xqk);
    cudaGetSymbolAddress((void**)&xvg,  g_xvg);
    cudaGetSymbolAddress((void**)&q,    g_q);
    cudaGetSymbolAddress((void**)&k,    g_k);
    cudaGetSymbolAddress((void**)&v,    g_v);
    cudaGetSymbolAddress((void**)&ke,   g_ke);
    cudaGetSymbolAddress((void**)&ba,   g_betaA);
    cudaGetSymbolAddress((void**)&aa,   g_aA);
    cudaGetSymbolAddress((void**)&dec,  g_dec);
    cudaGetSymbolAddress((void**)&bm,   g_bm);
    cudaGetSymbolAddress((void**)&opre, g_opre);
    cudaGetSymbolAddress((void**)&X3,   g_X3);
    cudaGetSymbolAddress((void**)&Wqk3, g_Wqk3);
    cudaGetSymbolAddress((void**)&Wvg3, g_Wvg3);
    cudaGetSymbolAddress((void**)&Wo3,  g_Wo3);
    cudaGetSymbolAddress((void**)&of3,  g_of3);
    cudaGetSymbolAddress((void**)&k3,   g_k3);
    cudaGetSymbolAddress((void**)&Wek3, g_Wek3);

    // split fp32 -> bf16 triples (combined weight buffers)
    split3_kernel<<<TOK_*HS_/256, 256>>>(X,  X3,  HS_, 1);
    split3_kernel<<<KD_*HS_/256, 256>>>(Wq, Wqk3,                        HS_, 0);
    split3_kernel<<<KD_*HS_/256, 256>>>(Wk, Wqk3 + (long long)KD_*3*HS_, HS_, 0);
    split3_kernel<<<VD_*HS_/256, 256>>>(Wv, Wvg3,                        HS_, 0);
    split3_kernel<<<VD_*HS_/256, 256>>>(Wg, Wvg3 + (long long)VD_*3*HS_, HS_, 0);
    split3_kernel<<<HS_*VD_/256, 256>>>(Wo, Wo3, VD_, 0);
    // W_ek flattened: (E*NH*HD) rows of HD, B-side
    split3_kernel<<<E_*NH_*HD_*HD_/256, 256>>>(Wek, Wek3, HD_, 0);

    // merged projections on HMMA tensor cores (K3 = 3*HS = 6144)
    hmma_gemm<<<dim3((2*KD_)/128, TOK_/128), 256>>>(X3, Wqk3, xqk, 3*HS_, 2*KD_);
    hmma_gemm<<<dim3((2*VD_)/128, TOK_/128), 256>>>(X3, Wvg3, xvg, 3*HS_, 2*VD_);
    proj_ba_kernel<<<TOK_, 256>>>(X, Wb, Wa, ba, aa);

    // causal conv + SiLU (inputs strided inside combined buffers)
    conv_silu_kernel<<<dim3(KD_/256, L_/64, B_), 256>>>(xqk,        cq, q, 2*KD_, KD_);
    conv_silu_kernel<<<dim3(KD_/256, L_/64, B_), 256>>>(xqk + KD_,  ck, k, 2*KD_, KD_);
    conv_silu_kernel<<<dim3(VD_/256, L_/64, B_), 256>>>(xvg,        cv, v, 2*VD_, VD_);

    // l2 norm per head row; q additionally scaled by HD^-0.5
    l2norm_kernel<<<TOK_*NH_/8, 256>>>(q, 0.0625f);
    l2norm_kernel<<<TOK_*NH_/8, 256>>>(k, 1.0f);

    // per-expert per-head key transform on HMMA (batched over e,h)
    split3_k_kernel<<<TOK_*KD_/256, 256>>>(k, k3);
    hmma_gemm_ke<<<dim3(HD_/128, TOK_/128, E_*NH_), 256>>>(k3, Wek3, ke);

    // gating scalars
    gating_kernel<<<(E_*B_*NH_*L_ + 255)/256, 256>>>(ba, aa, mod, Alog, dtb, dec, bm);

    // zero the expert-aggregated output accumulator
    zero_kernel<<<(TOK_*VD_/4 + 255)/256, 256>>>((float4*)opre, TOK_*VD_/4);

    // the sequential scan (packed f32x2 state + masked fast path)
    scan_kernel<<<E_*B_*NH_*NV_, 128>>>(q, ke, v, dec, bm, ow, opre);

    // RMSNorm + swish gate -> split-bf16 A operand
    norm_gate_kernel<<<TOK_*NH_, 128>>>(opre, xvg, onw, of3);

    // output projection on HMMA tensor cores (K3 = 3*VD = 12288)
    hmma_gemm<<<dim3(HS_/128, TOK_/128), 256>>>(of3, Wo3, out, 3*VD_, HS_);
}

// round 10
// speedup vs baseline: 2.3078x; 1.0316x over previous
#include <cuda_runtime.h>
#include <cuda_bf16.h>
#include <cstdint>
#include <math.h>

#define B_   2
#define L_   1024
#define HS_  2048
#define NH_  8
#define HD_  256
#define DV_  512
#define KD_  2048
#define VD_  4096
#define E_   3
#define TOK_ 2048
#define NV_  8
#define DVS_ 64
#define QKVG_ 12288    // merged row: q(2048) k(2048) v(4096) g(4096)

// ---------------- scratch (static device arrays; no allocation) ----------------
__device__ __align__(16) float g_xqkvg[TOK_*QKVG_];
__device__ __align__(16) float g_q [TOK_*KD_];
__device__ __align__(16) float g_k [TOK_*KD_];
__device__ __align__(16) float g_v [TOK_*VD_];
__device__ __align__(16) float g_ke[E_*TOK_*KD_];
__device__ __align__(16) float g_betaA[TOK_*E_*NH_];
__device__ __align__(16) float g_aA  [TOK_*E_*NH_];
__device__ __align__(16) float g_dec [E_*B_*NH_*L_];
__device__ __align__(16) float g_bm  [E_*B_*NH_*L_];
__device__ __align__(16) float g_opre[TOK_*VD_];

// split-bf16 buffers: A-side layout [hi | lo | hi], B-side layout [hi | hi | lo]
__device__ __align__(16) __nv_bfloat16 g_X3    [TOK_*3*HS_];
__device__ __align__(16) __nv_bfloat16 g_Wqkvg3[QKVG_*3*HS_];
__device__ __align__(16) __nv_bfloat16 g_Wo3   [HS_*3*VD_];
__device__ __align__(16) __nv_bfloat16 g_of3   [TOK_*3*VD_];
__device__ __align__(16) __nv_bfloat16 g_k3    [NH_*TOK_*3*HD_];
__device__ __align__(16) __nv_bfloat16 g_Wek3  [E_*NH_*HD_*3*HD_];

// ======================= helpers =============================================
__device__ __forceinline__ void cp16(uint32_t dst, const void* src) {
    asm volatile("cp.async.cg.shared.global [%0], [%1], 16;" :: "r"(dst), "l"(src));
}
#define CP_COMMIT() asm volatile("cp.async.commit_group;" ::: "memory")
#define CP_WAIT(n)  asm volatile("cp.async.wait_group %0;" :: "n"(n) : "memory")

#define MMA16816(d, a0, a1, a2, a3, b0, b1) \
    asm volatile("mma.sync.aligned.m16n8k16.row.col.f32.bf16.bf16.f32 " \
                 "{%0,%1,%2,%3}, {%4,%5,%6,%7}, {%8,%9}, {%0,%1,%2,%3};" \
                 : "+f"((d)[0]), "+f"((d)[1]), "+f"((d)[2]), "+f"((d)[3]) \
                 : "r"(a0), "r"(a1), "r"(a2), "r"(a3), "r"(b0), "r"(b1))

#define LDSM_X4(r, a) \
    asm volatile("ldmatrix.sync.aligned.m8n8.x4.shared.b16 {%0,%1,%2,%3}, [%4];" \
                 : "=r"((r)[0]), "=r"((r)[1]), "=r"((r)[2]), "=r"((r)[3]) : "r"(a))
#define LDSM_X2(r, a) \
    asm volatile("ldmatrix.sync.aligned.m8n8.x2.shared.b16 {%0,%1}, [%2];" \
                 : "=r"((r)[0]), "=r"((r)[1]) : "r"(a))

// packed f32x2 (Blackwell)
typedef unsigned long long u64;
__device__ __forceinline__ u64 pack2(float x, float y) {
    u64 r; asm("mov.b64 %0, {%1, %2};" : "=l"(r) : "f"(x), "f"(y)); return r;
}
__device__ __forceinline__ float2 unpack2(u64 v) {
    float2 f; asm("mov.b64 {%0, %1}, %2;" : "=f"(f.x), "=f"(f.y) : "l"(v)); return f;
}
#define FMA2(d, a, b, c) \
    asm("fma.rn.f32x2 %0, %1, %2, %3;" : "=l"(d) : "l"(a), "l"(b), "l"(c))
#define MUL2(d, a, b) \
    asm("mul.rn.f32x2 %0, %1, %2;" : "=l"(d) : "l"(a), "l"(b))

// ============== HMMA split-bf16 GEMM: C[M,N] = A3[M,K3] * B3[N,K3]^T ===========
// tile 128x128, BK=32, 256 threads (8 warps, 2x4), 3-stage cp.async pipeline,
// ldmatrix fragment loads. smem row stride 40 bf16 -> conflict-free.
#define BKC 32
#define SROW 40
#define STILE (128 * SROW)                 // elements per operand tile
#define NSTG 3
#define SMEM_DYN (NSTG * 2 * STILE * 2)    // 61440 bytes

struct HmmaCore {
    __device__ __forceinline__ static void run(
        const __nv_bfloat16* gAbase, const __nv_bfloat16* gBbase,
        float* C, int K3, int ldc, int bm, int bn, uint32_t sbase)
    {
        const int tid = threadIdx.x;
        const int lane = tid & 31, wid = tid >> 5;
        const int wm = wid >> 2;
        const int wn = wid & 3;
        const int grp = lane >> 2;
        const int qd  = lane & 3;
        const int NC = K3 / BKC;

        // ldmatrix per-lane base addresses (bytes)
        const int rA = lane & 15, hA = lane >> 4;        // A: row-in-16, k-half
        const int rB = lane & 7,  hB = (lane >> 3) & 1;  // B: row-in-8, k-half
        const uint32_t aAddr0 = sbase + (uint32_t)(((wm*64 + rA) * SROW + hA*8) * 2);
        const uint32_t bAddr0 = sbase + (uint32_t)(STILE*2) +
                                (uint32_t)(((wn*32 + rB) * SROW + hB*8) * 2);

        // loader: 512 x 16B per operand tile, 2+2 cp16 per thread
        const int lrow = tid >> 1;
        const int lch2 = (tid & 1) * 2;
        const __nv_bfloat16* gA = gAbase + (long long)(bm + lrow) * K3 + lch2 * 8;
        const __nv_bfloat16* gB = gBbase + (long long)(bn + lrow) * K3 + lch2 * 8;
        const uint32_t sA0 = sbase + (uint32_t)((lrow * SROW + lch2 * 8) * 2);
        const uint32_t sB0 = sA0 + (uint32_t)(STILE * 2);

        auto load_chunk = [&](int c, int s) {
            uint32_t off = (uint32_t)(s * 2 * STILE * 2);
            const __nv_bfloat16* pa = gA + (long long)c * BKC;
            const __nv_bfloat16* pb = gB + (long long)c * BKC;
            cp16(sA0 + off,      pa);
            cp16(sA0 + off + 16, pa + 8);
            cp16(sB0 + off,      pb);
            cp16(sB0 + off + 16, pb + 8);
            CP_COMMIT();
        };

        float acc[4][4][4];
#pragma unroll
        for (int i = 0; i < 4; i++)
#pragma unroll
            for (int j = 0; j < 4; j++)
#pragma unroll
                for (int r = 0; r < 4; r++) acc[i][j][r] = 0.f;

        load_chunk(0, 0);
        if (NC > 1) load_chunk(1, 1);

        for (int c = 0; c < NC; ++c) {
            const int s = c % NSTG;
            if (c + 2 < NC) { load_chunk(c + 2, (c + 2) % NSTG); CP_WAIT(2); }
            else if (c + 1 < NC) { CP_WAIT(1); }
            else { CP_WAIT(0); }
            __syncthreads();

            const uint32_t soff = (uint32_t)(s * 2 * STILE * 2);
#pragma unroll
            for (int kk = 0; kk < 2; ++kk) {
                const uint32_t kbyte = kk * 32;
                uint32_t af[4][4];
#pragma unroll
                for (int mt = 0; mt < 4; ++mt)
                    LDSM_X4(af[mt], aAddr0 + soff + (uint32_t)(mt * 16 * SROW * 2) + kbyte);
                uint32_t bf[4][2];
#pragma unroll
                for (int nt = 0; nt < 4; ++nt)
                    LDSM_X2(bf[nt], bAddr0 + soff + (uint32_t)(nt * 8 * SROW * 2) + kbyte);
#pragma unroll
                for (int mt = 0; mt < 4; ++mt)
#pragma unroll
                    for (int nt = 0; nt < 4; ++nt)
                        MMA16816(acc[mt][nt], af[mt][0], af[mt][1], af[mt][2], af[mt][3],
                                 bf[nt][0], bf[nt][1]);
            }
            __syncthreads();
        }

#pragma unroll
        for (int mt = 0; mt < 4; ++mt) {
            int row0 = bm + wm * 64 + mt * 16 + grp;
#pragma unroll
            for (int nt = 0; nt < 4; ++nt) {
                int col = bn + wn * 32 + nt * 8 + qd * 2;
                *reinterpret_cast<float2*>(&C[(long long)row0 * ldc + col]) =
                    make_float2(acc[mt][nt][0], acc[mt][nt][1]);
                *reinterpret_cast<float2*>(&C[(long long)(row0 + 8) * ldc + col]) =
                    make_float2(acc[mt][nt][2], acc[mt][nt][3]);
            }
        }
    }
};

__global__ __launch_bounds__(256) void hmma_gemm(
    const __nv_bfloat16* __restrict__ A, const __nv_bfloat16* __restrict__ B,
    float* __restrict__ C, int K3, int ldc)
{
    extern __shared__ __nv_bfloat16 smdyn[];
    HmmaCore::run(A, B, C, K3, ldc, blockIdx.y * 128, blockIdx.x * 128,
                  (uint32_t)__cvta_generic_to_shared(smdyn));
}

// batched over z = e*NH + h: ke[e][tok][h*HD + :] = k3[h] @ Wek3[e,h]^T
__global__ __launch_bounds__(256) void hmma_gemm_ke(
    const __nv_bfloat16* __restrict__ k3, const __nv_bfloat16* __restrict__ Wek3,
    float* __restrict__ ke)
{
    extern __shared__ __nv_bfloat16 smdyn[];
    const int z = blockIdx.z;
    const int e = z >> 3, h = z & 7;
    const __nv_bfloat16* A = k3  + (long long)h * TOK_ * (3*HD_);
    const __nv_bfloat16* B = Wek3 + (long long)z * HD_ * (3*HD_);
    float* C = ke + (long long)e * TOK_ * KD_ + h * HD_;
    HmmaCore::run(A, B, C, 3*HD_, KD_, blockIdx.y * 128, blockIdx.x * 128,
                  (uint32_t)__cvta_generic_to_shared(smdyn));
}

// ---------------- fp32 -> split-bf16 triple layout (8 elems/thread) -------------
// aSide=1 -> [h | l | h] (A operand);  aSide=0 -> [h | h | l] (B operand)
struct alignas(16) B8 { __nv_bfloat16 v[8]; };

__global__ void split3_kernel(const float* __restrict__ src, __nv_bfloat16* __restrict__ dst,
                              int K, int aSide)
{
    long long i8 = ((long long)blockIdx.x * 256 + threadIdx.x) * 8;
    int row = (int)(i8 / K);
    int col = (int)(i8 - (long long)row * K);
    float4 x0 = *reinterpret_cast<const float4*>(src + i8);
    float4 x1 = *reinterpret_cast<const float4*>(src + i8 + 4);
    float xs[8] = {x0.x, x0.y, x0.z, x0.w, x1.x, x1.y, x1.z, x1.w};
    B8 H, L;
#pragma unroll
    for (int j = 0; j < 8; ++j) {
        __nv_bfloat16 h = __float2bfloat16(xs[j]);
        H.v[j] = h;
        L.v[j] = __float2bfloat16(xs[j] - __bfloat162float(h));
    }
    long long b = (long long)row * (3LL * K) + col;
    *reinterpret_cast<B8*>(dst + b)          = H;
    *reinterpret_cast<B8*>(dst + b + K)      = aSide ? L : H;
    *reinterpret_cast<B8*>(dst + b + 2LL*K)  = aSide ? H : L;
}

// k [TOK][KD] fp32 -> k3 [NH][TOK][3*HD] split-bf16 A-side (8 elems/thread)
__global__ void split3_k_kernel(const float* __restrict__ k, __nv_bfloat16* __restrict__ k3)
{
    long long i8 = ((long long)blockIdx.x * 256 + threadIdx.x) * 8;
    int tok = (int)(i8 / KD_);
    int rem = (int)(i8 - (long long)tok * KD_);
    int h = rem >> 8;
    int d = rem & 255;
    float4 x0 = *reinterpret_cast<const float4*>(k + i8);
    float4 x1 = *reinterpret_cast<const float4*>(k + i8 + 4);
    float xs[8] = {x0.x, x0.y, x0.z, x0.w, x1.x, x1.y, x1.z, x1.w};
    B8 H, L;
#pragma unroll
    for (int j = 0; j < 8; ++j) {
        __nv_bfloat16 hb = __float2bfloat16(xs[j]);
        H.v[j] = hb;
        L.v[j] = __float2bfloat16(xs[j] - __bfloat162float(hb));
    }
    long long b = ((long long)h * TOK_ + tok) * (3LL*HD_) + d;
    *reinterpret_cast<B8*>(k3 + b)           = H;
    *reinterpret_cast<B8*>(k3 + b + HD_)     = L;
    *reinterpret_cast<B8*>(k3 + b + 2*HD_)   = H;
}

// ------------- small projection: beta_raw / a_raw = X @ {Wb,Wa}^T ---------------
__global__ __launch_bounds__(256) void proj_ba_kernel(
    const float* __restrict__ X, const float* __restrict__ Wb, const float* __restrict__ Wa,
    float* __restrict__ outB, float* __restrict__ outA)
{
    __shared__ float xs[HS_];
    int tok = blockIdx.x;
    const float* xr = X + (long long)tok * HS_;
    for (int i = threadIdx.x * 4; i < HS_; i += 256 * 4)
        *reinterpret_cast<float4*>(&xs[i]) = *reinterpret_cast<const float4*>(&xr[i]);
    __syncthreads();
    int warp = threadIdx.x >> 5, lane = threadIdx.x & 31;
    for (int j = warp; j < E_ * NH_; j += 8) {
        const float* wb = Wb + (long long)j * HS_;
        const float* wa = Wa + (long long)j * HS_;
        float sb = 0.f, sa = 0.f;
        for (int i = lane * 4; i < HS_; i += 32 * 4) {
            float4 xv = *reinterpret_cast<const float4*>(&xs[i]);
            float4 bv = *reinterpret_cast<const float4*>(&wb[i]);
            float4 av = *reinterpret_cast<const float4*>(&wa[i]);
            sb += xv.x*bv.x + xv.y*bv.y + xv.z*bv.z + xv.w*bv.w;
            sa += xv.x*av.x + xv.y*av.y + xv.z*av.z + xv.w*av.w;
        }
#pragma unroll
        for (int off = 16; off; off >>= 1) {
            sb += __shfl_xor_sync(0xffffffffu, sb, off);
            sa += __shfl_xor_sync(0xffffffffu, sa, off);
        }
        if (lane == 0) {
            outB[tok * (E_*NH_) + j] = sb;
            outA[tok * (E_*NH_) + j] = sa;
        }
    }
}

// -------- causal depthwise conv (K=4) + SiLU; input row stride CS, C channels ---
__global__ void conv_silu_kernel(const float* __restrict__ xin, const float* __restrict__ w,
                                 float* __restrict__ out, int CS, int C)
{
    int c  = blockIdx.x * 256 + threadIdx.x;
    int b  = blockIdx.z;
    int l0 = blockIdx.y * 64;
    float w0 = w[c*4+0], w1 = w[c*4+1], w2 = w[c*4+2], w3 = w[c*4+3];
    const float* xb = xin + (long long)b * L_ * CS + c;
    float*       ob = out + (long long)b * L_ * C  + c;
    float xm3 = (l0 >= 3) ? xb[(long long)(l0-3)*CS] : 0.f;
    float xm2 = (l0 >= 2) ? xb[(long long)(l0-2)*CS] : 0.f;
    float xm1 = (l0 >= 1) ? xb[(long long)(l0-1)*CS] : 0.f;
    for (int l = l0; l < l0 + 64; ++l) {
        float x0 = xb[(long long)l*CS];
        float y  = w0*xm3 + w1*xm2 + w2*xm1 + w3*x0;
        ob[(long long)l*C] = y / (1.f + expf(-y));
        xm3 = xm2; xm2 = xm1; xm1 = x0;
    }
}

// ---------------- l2 normalize rows of 256 (optionally * scale) ----------------
__global__ void l2norm_kernel(float* __restrict__ data, float scale)
{
    int warp = threadIdx.x >> 5;
    int lane = threadIdx.x & 31;
    long long row = (long long)blockIdx.x * 8 + warp;
    float* p = data + row * HD_ + lane * 8;
    float4 a = *reinterpret_cast<float4*>(p);
    float4 b = *reinterpret_cast<float4*>(p + 4);
    float s = a.x*a.x + a.y*a.y + a.z*a.z + a.w*a.w
            + b.x*b.x + b.y*b.y + b.z*b.z + b.w*b.w;
#pragma unroll
    for (int off = 16; off; off >>= 1) s += __shfl_xor_sync(0xffffffffu, s, off);
    float r = rsqrtf(s + 1e-6f) * scale;
    a.x *= r; a.y *= r; a.z *= r; a.w *= r;
    b.x *= r; b.y *= r; b.z *= r; b.w *= r;
    *reinterpret_cast<float4*>(p)     = a;
    *reinterpret_cast<float4*>(p + 4) = b;
}

// ---------------- gating: decay and beta*mask per (e,b,h,t) --------------------
__global__ void gating_kernel(const float* __restrict__ betaA, const float* __restrict__ aA,
                              const int* __restrict__ mod, const float* __restrict__ A_log,
                              const float* __restrict__ dtb,
                              float* __restrict__ dec, float* __restrict__ bm)
{
    int idx = blockIdx.x * 256 + threadIdx.x;
    if (idx >= E_*B_*NH_*L_) return;
    int t = idx % L_;
    int h = (idx / L_) % NH_;
    int b = (idx / (L_*NH_)) % B_;
    int e = idx / (L_*NH_*B_);
    int tok = b * L_ + t;
    int j = e * NH_ + h;
    float braw = betaA[tok*(E_*NH_) + j];
    float beta = 1.f / (1.f + expf(-braw));
    float av = aA[tok*(E_*NH_) + j] + dtb[j];
    float sp = (av > 20.f) ? av : log1pf(expf(av));
    float g  = -expf(A_log[j]) * sp;
    int mid  = mod[tok];
    float m  = (e == 0) ? 1.f : ((e == 1) ? (mid == 0 ? 1.f : 0.f)
                                          : (mid == 1 ? 1.f : 0.f));
    dec[idx] = expf(g) * m + (1.f - m);
    bm[idx]  = beta * m;
}

// ---------------- zero fill -----------------------------------------------------
__global__ void zero_kernel(float4* __restrict__ p, int n4)
{
    int i = blockIdx.x * 256 + threadIdx.x;
    if (i < n4) p[i] = make_float4(0.f, 0.f, 0.f, 0.f);
}

// ------- recurrent scan: packed f32x2 state, v-partitioned, masked fast path ----
__global__ __launch_bounds__(128) void scan_kernel(
    const float* __restrict__ qbuf, const float* __restrict__ kebuf,
    const float* __restrict__ vbuf, const float* __restrict__ decbuf,
    const float* __restrict__ bmbuf, const float* __restrict__ oww,
    float* __restrict__ opre)
{
    const int cta = blockIdx.x;
    const int vp = cta % NV_;
    const int h  = (cta / NV_) % NH_;
    const int b  = (cta / (NV_ * NH_)) % B_;
    const int e  = cta / (NV_ * NH_ * B_);
    const int tid = threadIdx.x;
    const int vl = tid >> 1;
    const int kh = tid & 1;
    const int vbase = vp * DVS_;

    float w0 = expf(oww[0*NH_ + h]);
    float w1 = expf(oww[1*NH_ + h]);
    float w2 = expf(oww[2*NH_ + h]);
    float wout = ((e == 0) ? w0 : ((e == 1) ? w1 : w2)) / (w0 + w1 + w2);

    __shared__ __align__(16) float ksm[2][264];
    __shared__ __align__(16) float qsm[2][264];

    u64 S2[64];
    const u64 z2 = pack2(0.f, 0.f);
#pragma unroll
    for (int j = 0; j < 64; j++) S2[j] = z2;

    const float* decp = decbuf + ((e*B_ + b)*NH_ + h) * L_;
    const float* bmp  = bmbuf  + ((e*B_ + b)*NH_ + h) * L_;
    const float* kp   = kebuf + (long long)e * TOK_ * KD_ + (long long)b * L_ * KD_ + h * HD_;
    const float* qp   = qbuf  + (long long)b * L_ * KD_ + h * HD_;
    const float* vp_  = vbuf  + (long long)b * L_ * VD_ + h * DV_ + vbase + vl;
    float*       op   = opre  + (long long)b * L_ * VD_ + h * DV_ + vbase + vl;

    const int koff = kh * 132;
    const int idx4 = tid & 63;
    const int halfoff = ((idx4 >> 5) * 132) + ((idx4 * 4) & 127);
    const bool loadk = (tid < 64);
    const float* mysrc = loadk ? kp : qp;

    // preload t = 0
    {
        float4 v4 = *reinterpret_cast<const float4*>(mysrc + idx4 * 4);
        float* dst = loadk ? &ksm[0][0] : &qsm[0][0];
        *reinterpret_cast<float4*>(dst + halfoff) = v4;
    }
    float dec_c = decp[0], bm_c = bmp[0], v_c = vp_[0];
    __syncthreads();

    for (int t = 0; t < L_; ++t) {
        const int cur = t & 1;
        float dec_n = 0.f, bm_n = 0.f, v_n = 0.f;
        if (t + 1 < L_) {
            float4 v4 = *reinterpret_cast<const float4*>(mysrc + (long long)(t+1) * KD_ + idx4 * 4);
            float* dst = loadk ? &ksm[cur ^ 1][0] : &qsm[cur ^ 1][0];
            *reinterpret_cast<float4*>(dst + halfoff) = v4;
            dec_n = decp[t+1]; bm_n = bmp[t+1]; v_n = vp_[(long long)(t+1) * VD_];
        }
        const float* kb = &ksm[cur][koff];
        const float* qb = &qsm[cur][koff];
        float o;

        if (bm_c != 0.f) {
            const u64 dd = pack2(dec_c, dec_c);
            u64 a0 = z2, a1 = z2;
#pragma unroll
            for (int j = 0; j < 128; j += 4) {
                ulonglong2 kk = *reinterpret_cast<const ulonglong2*>(kb + j);
                const int i = j >> 1;
                MUL2(S2[i],   S2[i],   dd);
                FMA2(a0, kk.x, S2[i],   a0);
                MUL2(S2[i+1], S2[i+1], dd);
                FMA2(a1, kk.y, S2[i+1], a1);
            }
            float2 f0 = unpack2(a0), f1 = unpack2(a1);
            float pred = (f0.x + f0.y) + (f1.x + f1.y);
            pred += __shfl_xor_sync(0xffffffffu, pred, 1);
            float delta = (v_c - pred) * bm_c;
            const u64 del2 = pack2(delta, delta);

            u64 b0 = z2, b1 = z2;
#pragma unroll
            for (int j = 0; j < 128; j += 4) {
                ulonglong2 kk = *reinterpret_cast<const ulonglong2*>(kb + j);
                ulonglong2 qq = *reinterpret_cast<const ulonglong2*>(qb + j);
                const int i = j >> 1;
                FMA2(S2[i],   kk.x, del2, S2[i]);
                FMA2(b0, qq.x, S2[i],   b0);
                FMA2(S2[i+1], kk.y, del2, S2[i+1]);
                FMA2(b1, qq.y, S2[i+1], b1);
            }
            float2 g0 = unpack2(b0), g1 = unpack2(b1);
            o = (g0.x + g0.y) + (g1.x + g1.y);
        } else {
            u64 b0 = z2, b1 = z2;
#pragma unroll
            for (int j = 0; j < 128; j += 4) {
                ulonglong2 qq = *reinterpret_cast<const ulonglong2*>(qb + j);
                const int i = j >> 1;
                FMA2(b0, qq.x, S2[i],   b0);
                FMA2(b1, qq.y, S2[i+1], b1);
            }
            float2 g0 = unpack2(b0), g1 = unpack2(b1);
            o = (g0.x + g0.y) + (g1.x + g1.y);
        }
        o += __shfl_xor_sync(0xffffffffu, o, 1);
        if (kh == 0) atomicAdd(&op[(long long)t * VD_], o * wout);

        __syncthreads();
        dec_c = dec_n; bm_c = bm_n; v_c = v_n;
    }
}

// -------- RMSNorm * weight * SiLU(gate), emitting split-bf16 A-operand ----------
// gate lives in xqkvg[tok][8192 + h*DV_ + i] (row stride QKVG_)
__global__ __launch_bounds__(128) void norm_gate_kernel(
    const float* __restrict__ opre, const float* __restrict__ xqkvg,
    const float* __restrict__ wnorm, __nv_bfloat16* __restrict__ out3)
{
    int row = blockIdx.x;                       // tok*NH + h
    int tok = row >> 3;
    int hh  = row & 7;
    long long base = (long long)row * DV_;
    const float* o = opre + base;
    const float* g = xqkvg + (long long)tok * QKVG_ + (2*KD_ + VD_) + hh * DV_;
    int i = threadIdx.x * 4;
    float4 ov = *reinterpret_cast<const float4*>(&o[i]);
    float ss = ov.x*ov.x + ov.y*ov.y + ov.z*ov.z + ov.w*ov.w;
#pragma unroll
    for (int off = 16; off; off >>= 1) ss += __shfl_xor_sync(0xffffffffu, ss, off);
    __shared__ float red[4];
    int warp = threadIdx.x >> 5, lane = threadIdx.x & 31;
    if (lane == 0) red[warp] = ss;
    __syncthreads();
    float tot = red[0] + red[1] + red[2] + red[3];
    float inv = rsqrtf(tot * (1.f / (float)DV_) + 1e-5f);
    float4 wv = *reinterpret_cast<const float4*>(&wnorm[i]);
    float4 gv = *reinterpret_cast<const float4*>(&g[i]);
    float r[4];
    r[0] = ov.x * inv * wv.x * (gv.x / (1.f + expf(-gv.x)));
    r[1] = ov.y * inv * wv.y * (gv.y / (1.f + expf(-gv.y)));
    r[2] = ov.z * inv * wv.z * (gv.z / (1.f + expf(-gv.z)));
    r[3] = ov.w * inv * wv.w * (gv.w / (1.f + expf(-gv.w)));
    int col = hh * DV_ + i;
    long long b3 = (long long)tok * (3LL * VD_) + col;
#pragma unroll
    for (int j = 0; j < 4; ++j) {
        __nv_bfloat16 hb = __float2bfloat16(r[j]);
        __nv_bfloat16 lb = __float2bfloat16(r[j] - __bfloat162float(hb));
        out3[b3 + j]            = hb;
        out3[b3 + VD_ + j]      = lb;
        out3[b3 + 2LL*VD_ + j]  = hb;
    }
}

// ================================ launch ======================================
extern "C" void kernel_launch(void* const* d_in, const int* in_sizes, int n_in,
                              void* d_out, int out_size)
{
    const float* X    = (const float*)d_in[0];
    const int*   mod  = (const int*)  d_in[1];
    const float* Wq   = (const float*)d_in[2];
    const float* Wk   = (const float*)d_in[3];
    const float* Wv   = (const float*)d_in[4];
    const float* cq   = (const float*)d_in[5];
    const float* ck   = (const float*)d_in[6];
    const float* cv   = (const float*)d_in[7];
    const float* Wek  = (const float*)d_in[8];
    const float* Wb   = (const float*)d_in[9];
    const float* Wa   = (const float*)d_in[10];
    const float* Alog = (const float*)d_in[11];
    const float* dtb  = (const float*)d_in[12];
    const float* ow   = (const float*)d_in[13];
    const float* Wg   = (const float*)d_in[14];
    const float* onw  = (const float*)d_in[15];
    const float* Wo   = (const float*)d_in[16];
    float* out = (float*)d_out;

    float *xqkvg, *q, *k, *v, *ke, *ba, *aa, *dec, *bm, *opre;
    __nv_bfloat16 *X3, *Wqkvg3, *Wo3, *of3, *k3, *Wek3;
    cudaGetSymbolAddress((void**)&xqkvg, g_xqkvg);
    cudaGetSymbolAddress((void**)&q,     g_q);
    cudaGetSymbolAddress((void**)&k,     g_k);
    cudaGetSymbolAddress((void**)&v,     g_v);
    cudaGetSymbolAddress((void**)&ke,    g_ke);
    cudaGetSymbolAddress((void**)&ba,    g_betaA);
    cudaGetSymbolAddress((void**)&aa,    g_aA);
    cudaGetSymbolAddress((void**)&dec,   g_dec);
    cudaGetSymbolAddress((void**)&bm,    g_bm);
    cudaGetSymbolAddress((void**)&opre,  g_opre);
    cudaGetSymbolAddress((void**)&X3,    g_X3);
    cudaGetSymbolAddress((void**)&Wqkvg3,g_Wqkvg3);
    cudaGetSymbolAddress((void**)&Wo3,   g_Wo3);
    cudaGetSymbolAddress((void**)&of3,   g_of3);
    cudaGetSymbolAddress((void**)&k3,    g_k3);
    cudaGetSymbolAddress((void**)&Wek3,  g_Wek3);

    cudaFuncSetAttribute(hmma_gemm,    cudaFuncAttributeMaxDynamicSharedMemorySize, SMEM_DYN);
    cudaFuncSetAttribute(hmma_gemm_ke, cudaFuncAttributeMaxDynamicSharedMemorySize, SMEM_DYN);

    // split fp32 -> bf16 triples (vectorized 8-wide)
    split3_kernel<<<TOK_*HS_/2048, 256>>>(X,  X3, HS_, 1);
    split3_kernel<<<KD_*HS_/2048, 256>>>(Wq, Wqkvg3,                                 HS_, 0);
    split3_kernel<<<KD_*HS_/2048, 256>>>(Wk, Wqkvg3 + (long long)KD_*3*HS_,          HS_, 0);
    split3_kernel<<<VD_*HS_/2048, 256>>>(Wv, Wqkvg3 + (long long)(2*KD_)*3*HS_,      HS_, 0);
    split3_kernel<<<VD_*HS_/2048, 256>>>(Wg, Wqkvg3 + (long long)(2*KD_+VD_)*3*HS_,  HS_, 0);
    split3_kernel<<<HS_*VD_/2048, 256>>>(Wo, Wo3, VD_, 0);
    split3_kernel<<<E_*NH_*HD_*HD_/2048, 256>>>(Wek, Wek3, HD_, 0);

    // one merged projection GEMM: [q|k|v|g] (K3 = 3*HS = 6144, N = 12288)
    hmma_gemm<<<dim3(QKVG_/128, TOK_/128), 256, SMEM_DYN>>>(X3, Wqkvg3, xqkvg, 3*HS_, QKVG_);
    proj_ba_kernel<<<TOK_, 256>>>(X, Wb, Wa, ba, aa);

    // causal conv + SiLU (inputs strided inside merged buffer)
    conv_silu_kernel<<<dim3(KD_/256, L_/64, B_), 256>>>(xqkvg,          cq, q, QKVG_, KD_);
    conv_silu_kernel<<<dim3(KD_/256, L_/64, B_), 256>>>(xqkvg + KD_,    ck, k, QKVG_, KD_);
    conv_silu_kernel<<<dim3(VD_/256, L_/64, B_), 256>>>(xqkvg + 2*KD_,  cv, v, QKVG_, VD_);

    // l2 norm per head row; q additionally scaled by HD^-0.5
    l2norm_kernel<<<TOK_*NH_/8, 256>>>(q, 0.0625f);
    l2norm_kernel<<<TOK_*NH_/8, 256>>>(k, 1.0f);

    // per-expert per-head key transform on HMMA (batched over e,h)
    split3_k_kernel<<<TOK_*KD_/2048, 256>>>(k, k3);
    hmma_gemm_ke<<<dim3(HD_/128, TOK_/128, E_*NH_), 256, SMEM_DYN>>>(k3, Wek3, ke);

    // gating scalars
    gating_kernel<<<(E_*B_*NH_*L_ + 255)/256, 256>>>(ba, aa, mod, Alog, dtb, dec, bm);

    // zero the expert-aggregated output accumulator
    zero_kernel<<<(TOK_*VD_/4 + 255)/256, 256>>>((float4*)opre, TOK_*VD_/4);

    // the sequential scan
    scan_kernel<<<E_*B_*NH_*NV_, 128>>>(q, ke, v, dec, bm, ow, opre);

    // RMSNorm + swish gate -> split-bf16 A operand
    norm_gate_kernel<<<TOK_*NH_, 128>>>(opre, xqkvg, onw, of3);

    // output projection (K3 = 3*VD = 12288)
    hmma_gemm<<<dim3(HS_/128, TOK_/128), 256, SMEM_DYN>>>(of3, Wo3, out, 3*VD_, HS_);
}